// round 1
// baseline (speedup 1.0000x reference)
#include <cuda_runtime.h>

// ---------------------------------------------------------------------------
// Problem constants: B=4, S=2048, D=1024, H=16, hd=64, causal mask
// ---------------------------------------------------------------------------
#define BATCH 4
#define SEQ   2048
#define DMODEL 1024
#define NHEAD 16
#define HDIM  64
#define TD    (3 * DMODEL)          // 3072, qkv row width
#define NEG_BIG -1e30f

// Scratch (allocation-free rule: __device__ globals)
__device__ float g_qkv[(size_t)BATCH * SEQ * TD];       // [B,S,3D]   96 MB
__device__ float g_attn[(size_t)BATCH * SEQ * DMODEL];  // [B,H,S,hd] 32 MB (flat == [8192,1024])

// ---------------------------------------------------------------------------
// SGEMM: C[M,N] = A[M,K] @ B[K,N] + bias[N].  128x128 tile, BK=8, 256 thr,
// 8x8 per thread. Assumes M%128==0, N%128==0, K%8==0, all f32, 16B aligned.
// ---------------------------------------------------------------------------
__global__ __launch_bounds__(256) void sgemm_bias_128x128(
    const float* __restrict__ A, const float* __restrict__ B,
    const float* __restrict__ bias, float* __restrict__ C,
    int M, int N, int K)
{
    __shared__ float As[8][128];   // A tile transposed: As[k][m]
    __shared__ float Bs[8][128];   // Bs[k][n]

    const int tid = threadIdx.x;
    const int bm  = blockIdx.y * 128;
    const int bn  = blockIdx.x * 128;
    const int tr  = tid >> 4;          // 0..15  -> rows tr*8..+7
    const int tc  = tid & 15;          // 0..15  -> cols tc*8..+7

    // load mapping
    const int arow = tid >> 1;              // 0..127
    const int acol = (tid & 1) * 4;         // 0 or 4
    const int brow = tid >> 5;              // 0..7
    const int bcol = (tid & 31) * 4;        // 0..124

    const float* Aptr = A + (size_t)(bm + arow) * K + acol;
    const float* Bptr = B + (size_t)brow * N + bn + bcol;

    float acc[8][8];
#pragma unroll
    for (int i = 0; i < 8; ++i)
#pragma unroll
        for (int j = 0; j < 8; ++j) acc[i][j] = 0.0f;

    for (int k0 = 0; k0 < K; k0 += 8) {
        float4 a4 = *(const float4*)(Aptr + k0);
        float4 b4 = *(const float4*)(Bptr + (size_t)k0 * N);
        As[acol + 0][arow] = a4.x;
        As[acol + 1][arow] = a4.y;
        As[acol + 2][arow] = a4.z;
        As[acol + 3][arow] = a4.w;
        *(float4*)&Bs[brow][bcol] = b4;
        __syncthreads();

#pragma unroll
        for (int kk = 0; kk < 8; ++kk) {
            float ra[8], rb[8];
            float4 ra0 = *(const float4*)&As[kk][tr * 8];
            float4 ra1 = *(const float4*)&As[kk][tr * 8 + 4];
            float4 rb0 = *(const float4*)&Bs[kk][tc * 8];
            float4 rb1 = *(const float4*)&Bs[kk][tc * 8 + 4];
            ra[0]=ra0.x; ra[1]=ra0.y; ra[2]=ra0.z; ra[3]=ra0.w;
            ra[4]=ra1.x; ra[5]=ra1.y; ra[6]=ra1.z; ra[7]=ra1.w;
            rb[0]=rb0.x; rb[1]=rb0.y; rb[2]=rb0.z; rb[3]=rb0.w;
            rb[4]=rb1.x; rb[5]=rb1.y; rb[6]=rb1.z; rb[7]=rb1.w;
#pragma unroll
            for (int i = 0; i < 8; ++i)
#pragma unroll
                for (int j = 0; j < 8; ++j)
                    acc[i][j] += ra[i] * rb[j];
        }
        __syncthreads();
    }

    // epilogue: add bias, vectorized stores
    float bv[8];
#pragma unroll
    for (int j = 0; j < 8; ++j) bv[j] = bias[bn + tc * 8 + j];

#pragma unroll
    for (int i = 0; i < 8; ++i) {
        float* crow = C + (size_t)(bm + tr * 8 + i) * N + bn + tc * 8;
        float4 o0 = make_float4(acc[i][0]+bv[0], acc[i][1]+bv[1],
                                acc[i][2]+bv[2], acc[i][3]+bv[3]);
        float4 o1 = make_float4(acc[i][4]+bv[4], acc[i][5]+bv[5],
                                acc[i][6]+bv[6], acc[i][7]+bv[7]);
        *(float4*)(crow)     = o0;
        *(float4*)(crow + 4) = o1;
    }
}

// ---------------------------------------------------------------------------
// Flash attention, fp32, causal.  One block = one (qtile=64 rows, head, batch).
// 256 threads as 16x16; each thread owns a 4x4 score fragment and a 4x4
// output fragment. Online softmax; P staged through smem for the PV gemm.
// q/k/v are slices of g_qkv row: [q(64) | k(64) | v(64)] at h*192.
// Output written in [B,H,S,hd] order (== reference reshape semantics).
// ---------------------------------------------------------------------------
#define LDT 65   // smem leading dim (2-way max conflicts)

__global__ __launch_bounds__(256) void attn_flash_kernel(
    const float* __restrict__ qkv, float* __restrict__ out,
    const int* __restrict__ maskp)
{
    const int qt = blockIdx.x;   // 0..31
    const int h  = blockIdx.y;   // 0..15
    const int b  = blockIdx.z;   // 0..3
    const int tid = threadIdx.x;
    const int ty = tid >> 4;     // 0..15 (query rows ty*4..+3)
    const int tx = tid & 15;     // 0..15 (key cols / out cols tx*4..+3)

    extern __shared__ float sm[];
    float* Qs = sm;                    // [64][LDT]
    float* Ks = Qs + 64 * LDT;
    float* Vs = Ks + 64 * LDT;
    float* Ps = Vs + 64 * LDT;

    const int use_mask = (maskp[0] != 0);
    const size_t base = (size_t)b * SEQ * TD + (size_t)h * (3 * HDIM);

    // ---- load Q tile (64x64) ----
    for (int i = tid; i < 64 * 16; i += 256) {
        int r = i >> 4, c4 = (i & 15) * 4;
        float4 q4 = *(const float4*)(qkv + base + (size_t)(qt * 64 + r) * TD + c4);
        Qs[r * LDT + c4 + 0] = q4.x;
        Qs[r * LDT + c4 + 1] = q4.y;
        Qs[r * LDT + c4 + 2] = q4.z;
        Qs[r * LDT + c4 + 3] = q4.w;
    }

    float O[4][4];
    float m_i[4], l_i[4];
#pragma unroll
    for (int i = 0; i < 4; ++i) {
        m_i[i] = -INFINITY; l_i[i] = 0.0f;
#pragma unroll
        for (int j = 0; j < 4; ++j) O[i][j] = 0.0f;
    }

    const int nkt = use_mask ? (qt + 1) : (SEQ / 64);

    for (int kt = 0; kt < nkt; ++kt) {
        __syncthreads();   // previous iter done with Ks/Vs/Ps (also covers Q load, iter 0)

        // ---- load K,V tiles (64x64 each) ----
        for (int i = tid; i < 64 * 16; i += 256) {
            int r = i >> 4, c4 = (i & 15) * 4;
            size_t rowoff = base + (size_t)(kt * 64 + r) * TD;
            float4 k4 = *(const float4*)(qkv + rowoff + HDIM + c4);
            float4 v4 = *(const float4*)(qkv + rowoff + 2 * HDIM + c4);
            Ks[r * LDT + c4 + 0] = k4.x; Ks[r * LDT + c4 + 1] = k4.y;
            Ks[r * LDT + c4 + 2] = k4.z; Ks[r * LDT + c4 + 3] = k4.w;
            Vs[r * LDT + c4 + 0] = v4.x; Vs[r * LDT + c4 + 1] = v4.y;
            Vs[r * LDT + c4 + 2] = v4.z; Vs[r * LDT + c4 + 3] = v4.w;
        }
        __syncthreads();

        // ---- scores: s[4][4] = Q(rows ty*4+i) . K(rows tx*4+j) ----
        float s[4][4];
#pragma unroll
        for (int i = 0; i < 4; ++i)
#pragma unroll
            for (int j = 0; j < 4; ++j) s[i][j] = 0.0f;

#pragma unroll 8
        for (int d = 0; d < 64; ++d) {
            float qv[4], kv[4];
#pragma unroll
            for (int i = 0; i < 4; ++i) qv[i] = Qs[(ty * 4 + i) * LDT + d];
#pragma unroll
            for (int j = 0; j < 4; ++j) kv[j] = Ks[(tx * 4 + j) * LDT + d];
#pragma unroll
            for (int i = 0; i < 4; ++i)
#pragma unroll
                for (int j = 0; j < 4; ++j)
                    s[i][j] += qv[i] * kv[j];
        }

        // scale + causal mask (only the diagonal tile needs masking)
#pragma unroll
        for (int i = 0; i < 4; ++i)
#pragma unroll
            for (int j = 0; j < 4; ++j) {
                s[i][j] *= 0.125f;   // 1/sqrt(64)
                if (use_mask && kt == qt && (tx * 4 + j) > (ty * 4 + i))
                    s[i][j] = NEG_BIG;
            }

        // ---- online softmax ----
        float rmax[4];
#pragma unroll
        for (int i = 0; i < 4; ++i) {
            rmax[i] = fmaxf(fmaxf(s[i][0], s[i][1]), fmaxf(s[i][2], s[i][3]));
#pragma unroll
            for (int off = 8; off > 0; off >>= 1)
                rmax[i] = fmaxf(rmax[i], __shfl_xor_sync(0xffffffffu, rmax[i], off));
        }
        float alpha[4];
#pragma unroll
        for (int i = 0; i < 4; ++i) {
            float mnew = fmaxf(m_i[i], rmax[i]);
            alpha[i] = __expf(m_i[i] - mnew);
            m_i[i] = mnew;
        }
        float rsum[4];
#pragma unroll
        for (int i = 0; i < 4; ++i) {
            rsum[i] = 0.0f;
#pragma unroll
            for (int j = 0; j < 4; ++j) {
                s[i][j] = __expf(s[i][j] - m_i[i]);
                rsum[i] += s[i][j];
            }
#pragma unroll
            for (int off = 8; off > 0; off >>= 1)
                rsum[i] += __shfl_xor_sync(0xffffffffu, rsum[i], off);
            l_i[i] = l_i[i] * alpha[i] + rsum[i];
#pragma unroll
            for (int j = 0; j < 4; ++j) O[i][j] *= alpha[i];
        }

        // ---- stage P to smem, then O += P @ V ----
#pragma unroll
        for (int i = 0; i < 4; ++i)
#pragma unroll
            for (int j = 0; j < 4; ++j)
                Ps[(ty * 4 + i) * LDT + tx * 4 + j] = s[i][j];
        __syncthreads();

#pragma unroll 8
        for (int kc = 0; kc < 64; ++kc) {
            float pv[4], vv[4];
#pragma unroll
            for (int i = 0; i < 4; ++i) pv[i] = Ps[(ty * 4 + i) * LDT + kc];
#pragma unroll
            for (int j = 0; j < 4; ++j) vv[j] = Vs[kc * LDT + tx * 4 + j];
#pragma unroll
            for (int i = 0; i < 4; ++i)
#pragma unroll
                for (int j = 0; j < 4; ++j)
                    O[i][j] += pv[i] * vv[j];
        }
    }

    // ---- epilogue: normalize, write [B,H,S,hd] contiguous ----
    const size_t obase = ((size_t)(b * NHEAD + h) * SEQ + qt * 64) * HDIM;
#pragma unroll
    for (int i = 0; i < 4; ++i) {
        float inv_l = 1.0f / l_i[i];
        float4 o4 = make_float4(O[i][0] * inv_l, O[i][1] * inv_l,
                                O[i][2] * inv_l, O[i][3] * inv_l);
        *(float4*)(out + obase + (size_t)(ty * 4 + i) * HDIM + tx * 4) = o4;
    }
}

// ---------------------------------------------------------------------------
// Launch: QKV gemm -> flash attention -> output gemm
// ---------------------------------------------------------------------------
extern "C" void kernel_launch(void* const* d_in, const int* in_sizes, int n_in,
                              void* d_out, int out_size)
{
    const float* x     = (const float*)d_in[0];
    const float* W_qkv = (const float*)d_in[1];
    const float* b_qkv = (const float*)d_in[2];
    const float* W_out = (const float*)d_in[3];
    const float* b_out = (const float*)d_in[4];
    const int*   maskp = (const int*)d_in[5];
    float* outp = (float*)d_out;

    float *qkv, *attn;
    cudaGetSymbolAddress((void**)&qkv, g_qkv);
    cudaGetSymbolAddress((void**)&attn, g_attn);

    const int M = BATCH * SEQ;   // 8192

    // QKV projection: [8192,1024] @ [1024,3072]
    {
        dim3 grid(TD / 128, M / 128);
        sgemm_bias_128x128<<<grid, 256>>>(x, W_qkv, b_qkv, qkv, M, TD, DMODEL);
    }

    // Flash attention
    {
        const int smem = 4 * 64 * LDT * sizeof(float);   // 66560 B
        cudaFuncSetAttribute(attn_flash_kernel,
                             cudaFuncAttributeMaxDynamicSharedMemorySize, smem);
        dim3 grid(SEQ / 64, NHEAD, BATCH);
        attn_flash_kernel<<<grid, 256, smem>>>(qkv, attn, maskp);
    }

    // Output projection: [8192,1024] @ [1024,1024]
    {
        dim3 grid(DMODEL / 128, M / 128);
        sgemm_bias_128x128<<<grid, 256>>>(attn, W_out, b_out, outp, M, DMODEL, DMODEL);
    }
}

// round 3
// speedup vs baseline: 1.4497x; 1.4497x over previous
#include <cuda_runtime.h>
#include <cuda_bf16.h>
#include <cstdint>

// ---------------------------------------------------------------------------
// Problem constants: B=4, S=2048, D=1024, H=16, hd=64, causal mask
// ---------------------------------------------------------------------------
#define BATCH 4
#define SEQ   2048
#define DMODEL 1024
#define NHEAD 16
#define HDIM  64
#define TD    (3 * DMODEL)          // 3072
#define MTOT  (BATCH * SEQ)         // 8192
#define NEG_BIG -1e30f

// Scratch (__device__ globals — allocation-free rule)
__device__ float         g_qkv[(size_t)MTOT * TD];        // [B,S,3D] fp32
__device__ __nv_bfloat16 g_xhi[(size_t)MTOT * DMODEL];
__device__ __nv_bfloat16 g_xlo[(size_t)MTOT * DMODEL];
__device__ __nv_bfloat16 g_w1hi[(size_t)TD * DMODEL];     // W_qkv^T [3072,1024]
__device__ __nv_bfloat16 g_w1lo[(size_t)TD * DMODEL];
__device__ __nv_bfloat16 g_w2hi[(size_t)DMODEL * DMODEL]; // W_out^T [1024,1024]
__device__ __nv_bfloat16 g_w2lo[(size_t)DMODEL * DMODEL];
__device__ __nv_bfloat16 g_ohi[(size_t)MTOT * DMODEL];    // attn out hi/lo
__device__ __nv_bfloat16 g_olo[(size_t)MTOT * DMODEL];

// ---------------------------------------------------------------------------
// mma.sync / ldmatrix helpers (sm_80+ PTX — works on plain sm_103 target)
// ---------------------------------------------------------------------------
__device__ __forceinline__ void cpasync16(uint32_t dst, const void* src) {
    asm volatile("cp.async.cg.shared.global [%0], [%1], 16;" :: "r"(dst), "l"(src));
}
__device__ __forceinline__ void ldsm_x4(uint32_t* r, uint32_t addr) {
    asm volatile("ldmatrix.sync.aligned.m8n8.x4.shared.b16 {%0,%1,%2,%3}, [%4];"
                 : "=r"(r[0]), "=r"(r[1]), "=r"(r[2]), "=r"(r[3]) : "r"(addr));
}
__device__ __forceinline__ void ldsm_x2(uint32_t* r, uint32_t addr) {
    asm volatile("ldmatrix.sync.aligned.m8n8.x2.shared.b16 {%0,%1}, [%2];"
                 : "=r"(r[0]), "=r"(r[1]) : "r"(addr));
}
__device__ __forceinline__ void mma_bf16(float* d, const uint32_t* a, const uint32_t* b) {
    asm volatile("mma.sync.aligned.m16n8k16.row.col.f32.bf16.bf16.f32 "
                 "{%0,%1,%2,%3}, {%4,%5,%6,%7}, {%8,%9}, {%0,%1,%2,%3};"
                 : "+f"(d[0]), "+f"(d[1]), "+f"(d[2]), "+f"(d[3])
                 : "r"(a[0]), "r"(a[1]), "r"(a[2]), "r"(a[3]),
                   "r"(b[0]), "r"(b[1]));
}

// ---------------------------------------------------------------------------
// Split / transpose conversion kernels
// ---------------------------------------------------------------------------
__global__ __launch_bounds__(256) void split_fp32_kernel(
    const float4* __restrict__ in, __nv_bfloat162* __restrict__ hi,
    __nv_bfloat162* __restrict__ lo, int n4)
{
    int i = blockIdx.x * 256 + threadIdx.x;
    if (i >= n4) return;
    float4 v = in[i];
    __nv_bfloat16 h0 = __float2bfloat16(v.x), h1 = __float2bfloat16(v.y);
    __nv_bfloat16 h2 = __float2bfloat16(v.z), h3 = __float2bfloat16(v.w);
    __nv_bfloat162 a, b, c, d;
    a.x = h0; a.y = h1; b.x = h2; b.y = h3;
    c.x = __float2bfloat16(v.x - __bfloat162float(h0));
    c.y = __float2bfloat16(v.y - __bfloat162float(h1));
    d.x = __float2bfloat16(v.z - __bfloat162float(h2));
    d.y = __float2bfloat16(v.w - __bfloat162float(h3));
    hi[2*i] = a; hi[2*i+1] = b;
    lo[2*i] = c; lo[2*i+1] = d;
}

// W[K,N] fp32 -> Bop[N,K] bf16 hi/lo (transpose + split)
__global__ __launch_bounds__(256) void transpose_split_kernel(
    const float* __restrict__ W, __nv_bfloat16* __restrict__ bhi,
    __nv_bfloat16* __restrict__ blo, int K, int N)
{
    __shared__ float t[32][33];
    int nb = blockIdx.x * 32, kb = blockIdx.y * 32;
    int tx = threadIdx.x & 31, ty = threadIdx.x >> 5;
#pragma unroll
    for (int i = 0; i < 4; ++i)
        t[ty + i * 8][tx] = W[(size_t)(kb + ty + i * 8) * N + nb + tx];
    __syncthreads();
#pragma unroll
    for (int i = 0; i < 4; ++i) {
        int n = nb + ty + i * 8;
        int k = kb + tx;
        float v = t[tx][ty + i * 8];
        __nv_bfloat16 h = __float2bfloat16(v);
        bhi[(size_t)n * K + k] = h;
        blo[(size_t)n * K + k] = __float2bfloat16(v - __bfloat162float(h));
    }
}

// ---------------------------------------------------------------------------
// bf16x3 HMMA GEMM: C[M,N] = A[M,K] @ Bop[N,K]^T + bias  (fp32 in/out via
// hi/lo bf16 splits; acc += Ahi*Bhi + Ahi*Blo + Alo*Bhi in fp32).
// 128x128 CTA tile, BK=32, 8 warps (2x4), double-buffered cp.async.
// ---------------------------------------------------------------------------
#define PITCHB 80                       // padded row bytes (32 bf16 + 8 pad)
#define TILEB (128 * PITCHB)            // 10240 per operand tile
#define STAGEB (4 * TILEB)              // 40960: Ahi|Alo|Bhi|Blo
#define GSMEM (2 * STAGEB)              // 81920

__device__ __forceinline__ void g_load_chunk(uint32_t stage,
    const __nv_bfloat16* __restrict__ Ahi, const __nv_bfloat16* __restrict__ Alo,
    const __nv_bfloat16* __restrict__ Bhi, const __nv_bfloat16* __restrict__ Blo,
    int m0, int n0, int kc, int K, int tid)
{
#pragma unroll
    for (int t = 0; t < 8; ++t) {
        int tile = t >> 1;
        int idx = ((t & 1) << 8) + tid;      // 0..511
        int row = idx >> 2;                  // 0..127
        int seg = idx & 3;                   // 16B chunk within 64B row
        uint32_t dst = stage + tile * TILEB + row * PITCHB + (seg << 4);
        size_t koff = (size_t)kc + (seg << 3);
        const __nv_bfloat16* src;
        if (tile == 0)      src = Ahi + (size_t)(m0 + row) * K + koff;
        else if (tile == 1) src = Alo + (size_t)(m0 + row) * K + koff;
        else if (tile == 2) src = Bhi + (size_t)(n0 + row) * K + koff;
        else                src = Blo + (size_t)(n0 + row) * K + koff;
        cpasync16(dst, src);
    }
}

__global__ __launch_bounds__(256) void gemm_bf16x3(
    const __nv_bfloat16* __restrict__ Ahi, const __nv_bfloat16* __restrict__ Alo,
    const __nv_bfloat16* __restrict__ Bhi, const __nv_bfloat16* __restrict__ Blo,
    const float* __restrict__ bias, float* __restrict__ C,
    int M, int N, int K)
{
    extern __shared__ char smem[];
    const uint32_t sbase = (uint32_t)__cvta_generic_to_shared(smem);

    const int tid  = threadIdx.x;
    const int wid  = tid >> 5;
    const int lane = tid & 31;
    const int wm   = wid >> 2;         // 0..1  (64-row slab)
    const int wn   = wid & 3;          // 0..3  (32-col slab)
    const int m0 = blockIdx.y * 128;
    const int n0 = blockIdx.x * 128;
    const int NC = K >> 5;             // BK=32 chunks

    float acc[4][4][4];
#pragma unroll
    for (int i = 0; i < 4; ++i)
#pragma unroll
        for (int j = 0; j < 4; ++j)
#pragma unroll
            for (int c = 0; c < 4; ++c) acc[i][j][c] = 0.0f;

    // ldmatrix lane address components (within a stage)
    const uint32_t a_row = (uint32_t)(wm * 64 + (lane & 15)) * PITCHB + ((lane >> 4) << 4);
    const uint32_t b_row = (uint32_t)(wn * 32 + (lane & 7)) * PITCHB + (((lane >> 3) & 1) << 4);

    g_load_chunk(sbase, Ahi, Alo, Bhi, Blo, m0, n0, 0, K, tid);
    asm volatile("cp.async.commit_group;");

    for (int k0 = 0; k0 < NC; ++k0) {
        uint32_t buf = (uint32_t)(k0 & 1) * STAGEB;
        if (k0 + 1 < NC) {
            g_load_chunk(sbase + (uint32_t)((k0 + 1) & 1) * STAGEB,
                         Ahi, Alo, Bhi, Blo, m0, n0, (k0 + 1) << 5, K, tid);
            asm volatile("cp.async.commit_group;");
            asm volatile("cp.async.wait_group 1;");
        } else {
            asm volatile("cp.async.wait_group 0;");
        }
        __syncthreads();

        const uint32_t sAhi = sbase + buf;
        const uint32_t sAlo = sAhi + TILEB;
        const uint32_t sBhi = sAlo + TILEB;
        const uint32_t sBlo = sBhi + TILEB;

#pragma unroll
        for (int kk = 0; kk < 2; ++kk) {
            const uint32_t kb = kk << 5;   // 16 bf16 = 32 bytes
            uint32_t ah[4][4], al[4][4], bh[4][2], bl[4][2];
#pragma unroll
            for (int mi = 0; mi < 4; ++mi) {
                uint32_t off = a_row + (uint32_t)(mi * 16) * PITCHB + kb;
                ldsm_x4(ah[mi], sAhi + off);
                ldsm_x4(al[mi], sAlo + off);
            }
#pragma unroll
            for (int ni = 0; ni < 4; ++ni) {
                uint32_t off = b_row + (uint32_t)(ni * 8) * PITCHB + kb;
                ldsm_x2(bh[ni], sBhi + off);
                ldsm_x2(bl[ni], sBlo + off);
            }
#pragma unroll
            for (int mi = 0; mi < 4; ++mi)
#pragma unroll
                for (int ni = 0; ni < 4; ++ni) {
                    mma_bf16(acc[mi][ni], ah[mi], bh[ni]);
                    mma_bf16(acc[mi][ni], ah[mi], bl[ni]);
                    mma_bf16(acc[mi][ni], al[mi], bh[ni]);
                }
        }
        __syncthreads();
    }

    // epilogue: fragment (mi,ni): lane holds rows r, r+8; cols 2*(lane&3)+{0,1}
    const int rbase = m0 + wm * 64 + (lane >> 2);
    const int cbase = n0 + wn * 32 + ((lane & 3) << 1);
#pragma unroll
    for (int mi = 0; mi < 4; ++mi)
#pragma unroll
        for (int ni = 0; ni < 4; ++ni) {
            int r = rbase + mi * 16;
            int c = cbase + ni * 8;
            float b0 = bias[c], b1 = bias[c + 1];
            float2 o0 = make_float2(acc[mi][ni][0] + b0, acc[mi][ni][1] + b1);
            float2 o1 = make_float2(acc[mi][ni][2] + b0, acc[mi][ni][3] + b1);
            *(float2*)(C + (size_t)r * N + c)       = o0;
            *(float2*)(C + (size_t)(r + 8) * N + c) = o1;
        }
}

// ---------------------------------------------------------------------------
// Flash attention, fp32, causal (round-1 kernel; epilogue emits bf16 hi/lo)
// ---------------------------------------------------------------------------
#define LDT 65

__global__ __launch_bounds__(256) void attn_flash_kernel(
    const float* __restrict__ qkv,
    __nv_bfloat16* __restrict__ ohi, __nv_bfloat16* __restrict__ olo,
    const int* __restrict__ maskp)
{
    const int qt = blockIdx.x;
    const int h  = blockIdx.y;
    const int b  = blockIdx.z;
    const int tid = threadIdx.x;
    const int ty = tid >> 4;
    const int tx = tid & 15;

    extern __shared__ float sm[];
    float* Qs = sm;
    float* Ks = Qs + 64 * LDT;
    float* Vs = Ks + 64 * LDT;
    float* Ps = Vs + 64 * LDT;

    const int use_mask = (maskp[0] != 0);
    const size_t base = (size_t)b * SEQ * TD + (size_t)h * (3 * HDIM);

    for (int i = tid; i < 64 * 16; i += 256) {
        int r = i >> 4, c4 = (i & 15) * 4;
        float4 q4 = *(const float4*)(qkv + base + (size_t)(qt * 64 + r) * TD + c4);
        Qs[r * LDT + c4 + 0] = q4.x; Qs[r * LDT + c4 + 1] = q4.y;
        Qs[r * LDT + c4 + 2] = q4.z; Qs[r * LDT + c4 + 3] = q4.w;
    }

    float O[4][4];
    float m_i[4], l_i[4];
#pragma unroll
    for (int i = 0; i < 4; ++i) {
        m_i[i] = -INFINITY; l_i[i] = 0.0f;
#pragma unroll
        for (int j = 0; j < 4; ++j) O[i][j] = 0.0f;
    }

    const int nkt = use_mask ? (qt + 1) : (SEQ / 64);

    for (int kt = 0; kt < nkt; ++kt) {
        __syncthreads();
        for (int i = tid; i < 64 * 16; i += 256) {
            int r = i >> 4, c4 = (i & 15) * 4;
            size_t rowoff = base + (size_t)(kt * 64 + r) * TD;
            float4 k4 = *(const float4*)(qkv + rowoff + HDIM + c4);
            float4 v4 = *(const float4*)(qkv + rowoff + 2 * HDIM + c4);
            Ks[r * LDT + c4 + 0] = k4.x; Ks[r * LDT + c4 + 1] = k4.y;
            Ks[r * LDT + c4 + 2] = k4.z; Ks[r * LDT + c4 + 3] = k4.w;
            Vs[r * LDT + c4 + 0] = v4.x; Vs[r * LDT + c4 + 1] = v4.y;
            Vs[r * LDT + c4 + 2] = v4.z; Vs[r * LDT + c4 + 3] = v4.w;
        }
        __syncthreads();

        float s[4][4];
#pragma unroll
        for (int i = 0; i < 4; ++i)
#pragma unroll
            for (int j = 0; j < 4; ++j) s[i][j] = 0.0f;

#pragma unroll 8
        for (int d = 0; d < 64; ++d) {
            float qv[4], kv[4];
#pragma unroll
            for (int i = 0; i < 4; ++i) qv[i] = Qs[(ty * 4 + i) * LDT + d];
#pragma unroll
            for (int j = 0; j < 4; ++j) kv[j] = Ks[(tx * 4 + j) * LDT + d];
#pragma unroll
            for (int i = 0; i < 4; ++i)
#pragma unroll
                for (int j = 0; j < 4; ++j)
                    s[i][j] += qv[i] * kv[j];
        }

#pragma unroll
        for (int i = 0; i < 4; ++i)
#pragma unroll
            for (int j = 0; j < 4; ++j) {
                s[i][j] *= 0.125f;
                if (use_mask && kt == qt && (tx * 4 + j) > (ty * 4 + i))
                    s[i][j] = NEG_BIG;
            }

        float rmax[4];
#pragma unroll
        for (int i = 0; i < 4; ++i) {
            rmax[i] = fmaxf(fmaxf(s[i][0], s[i][1]), fmaxf(s[i][2], s[i][3]));
#pragma unroll
            for (int off = 8; off > 0; off >>= 1)
                rmax[i] = fmaxf(rmax[i], __shfl_xor_sync(0xffffffffu, rmax[i], off));
        }
        float alpha[4];
#pragma unroll
        for (int i = 0; i < 4; ++i) {
            float mnew = fmaxf(m_i[i], rmax[i]);
            alpha[i] = __expf(m_i[i] - mnew);
            m_i[i] = mnew;
        }
        float rsum[4];
#pragma unroll
        for (int i = 0; i < 4; ++i) {
            rsum[i] = 0.0f;
#pragma unroll
            for (int j = 0; j < 4; ++j) {
                s[i][j] = __expf(s[i][j] - m_i[i]);
                rsum[i] += s[i][j];
            }
#pragma unroll
            for (int off = 8; off > 0; off >>= 1)
                rsum[i] += __shfl_xor_sync(0xffffffffu, rsum[i], off);
            l_i[i] = l_i[i] * alpha[i] + rsum[i];
#pragma unroll
            for (int j = 0; j < 4; ++j) O[i][j] *= alpha[i];
        }

#pragma unroll
        for (int i = 0; i < 4; ++i)
#pragma unroll
            for (int j = 0; j < 4; ++j)
                Ps[(ty * 4 + i) * LDT + tx * 4 + j] = s[i][j];
        __syncthreads();

#pragma unroll 8
        for (int kc = 0; kc < 64; ++kc) {
            float pv[4], vv[4];
#pragma unroll
            for (int i = 0; i < 4; ++i) pv[i] = Ps[(ty * 4 + i) * LDT + kc];
#pragma unroll
            for (int j = 0; j < 4; ++j) vv[j] = Vs[kc * LDT + tx * 4 + j];
#pragma unroll
            for (int i = 0; i < 4; ++i)
#pragma unroll
                for (int j = 0; j < 4; ++j)
                    O[i][j] += pv[i] * vv[j];
        }
    }

    const size_t obase = ((size_t)(b * NHEAD + h) * SEQ + qt * 64) * HDIM;
#pragma unroll
    for (int i = 0; i < 4; ++i) {
        float inv_l = 1.0f / l_i[i];
        size_t p = obase + (size_t)(ty * 4 + i) * HDIM + tx * 4;
#pragma unroll
        for (int j = 0; j < 4; ++j) {
            float v = O[i][j] * inv_l;
            __nv_bfloat16 hv = __float2bfloat16(v);
            ohi[p + j] = hv;
            olo[p + j] = __float2bfloat16(v - __bfloat162float(hv));
        }
    }
}

// ---------------------------------------------------------------------------
// Launch
// ---------------------------------------------------------------------------
extern "C" void kernel_launch(void* const* d_in, const int* in_sizes, int n_in,
                              void* d_out, int out_size)
{
    const float* x     = (const float*)d_in[0];
    const float* W_qkv = (const float*)d_in[1];
    const float* b_qkv = (const float*)d_in[2];
    const float* W_out = (const float*)d_in[3];
    const float* b_out = (const float*)d_in[4];
    const int*   maskp = (const int*)d_in[5];
    float* outp = (float*)d_out;

    float *qkv;
    __nv_bfloat16 *xhi, *xlo, *w1hi, *w1lo, *w2hi, *w2lo, *ohi, *olo;
    cudaGetSymbolAddress((void**)&qkv,  g_qkv);
    cudaGetSymbolAddress((void**)&xhi,  g_xhi);
    cudaGetSymbolAddress((void**)&xlo,  g_xlo);
    cudaGetSymbolAddress((void**)&w1hi, g_w1hi);
    cudaGetSymbolAddress((void**)&w1lo, g_w1lo);
    cudaGetSymbolAddress((void**)&w2hi, g_w2hi);
    cudaGetSymbolAddress((void**)&w2lo, g_w2lo);
    cudaGetSymbolAddress((void**)&ohi,  g_ohi);
    cudaGetSymbolAddress((void**)&olo,  g_olo);

    // 1) split x -> bf16 hi/lo
    {
        int n4 = MTOT * DMODEL / 4;
        split_fp32_kernel<<<(n4 + 255) / 256, 256>>>(
            (const float4*)x, (__nv_bfloat162*)xhi, (__nv_bfloat162*)xlo, n4);
    }
    // 2) transpose+split weights
    {
        dim3 g1(TD / 32, DMODEL / 32);
        transpose_split_kernel<<<g1, 256>>>(W_qkv, w1hi, w1lo, DMODEL, TD);
        dim3 g2(DMODEL / 32, DMODEL / 32);
        transpose_split_kernel<<<g2, 256>>>(W_out, w2hi, w2lo, DMODEL, DMODEL);
    }
    // 3) QKV projection (HMMA bf16x3): [8192,1024] @ [1024,3072]
    {
        cudaFuncSetAttribute(gemm_bf16x3,
                             cudaFuncAttributeMaxDynamicSharedMemorySize, GSMEM);
        dim3 grid(TD / 128, MTOT / 128);
        gemm_bf16x3<<<grid, 256, GSMEM>>>(xhi, xlo, w1hi, w1lo,
                                          b_qkv, qkv, MTOT, TD, DMODEL);
    }
    // 4) flash attention (fp32), epilogue emits hi/lo split
    {
        const int smem = 4 * 64 * LDT * sizeof(float);
        cudaFuncSetAttribute(attn_flash_kernel,
                             cudaFuncAttributeMaxDynamicSharedMemorySize, smem);
        dim3 grid(SEQ / 64, NHEAD, BATCH);
        attn_flash_kernel<<<grid, 256, smem>>>(qkv, ohi, olo, maskp);
    }
    // 5) output projection (HMMA bf16x3): [8192,1024] @ [1024,1024]
    {
        dim3 grid(DMODEL / 128, MTOT / 128);
        gemm_bf16x3<<<grid, 256, GSMEM>>>(ohi, olo, w2hi, w2lo,
                                          b_out, outp, MTOT, DMODEL, DMODEL);
    }
}

// round 4
// speedup vs baseline: 2.8141x; 1.9411x over previous
#include <cuda_runtime.h>
#include <cuda_bf16.h>
#include <cstdint>

// ---------------------------------------------------------------------------
// Problem constants: B=4, S=2048, D=1024, H=16, hd=64, causal mask
// ---------------------------------------------------------------------------
#define BATCH 4
#define SEQ   2048
#define DMODEL 1024
#define NHEAD 16
#define HDIM  64
#define TD    (3 * DMODEL)          // 3072
#define MTOT  (BATCH * SEQ)         // 8192
#define NEG_BIG -1e30f

// Scratch (__device__ globals — allocation-free rule)
__device__ __nv_bfloat16 g_qkvhi[(size_t)MTOT * TD];      // [B,S,3D] bf16 hi
__device__ __nv_bfloat16 g_qkvlo[(size_t)MTOT * TD];      // [B,S,3D] bf16 lo
__device__ __nv_bfloat16 g_xhi[(size_t)MTOT * DMODEL];
__device__ __nv_bfloat16 g_xlo[(size_t)MTOT * DMODEL];
__device__ __nv_bfloat16 g_w1hi[(size_t)TD * DMODEL];     // W_qkv^T [3072,1024]
__device__ __nv_bfloat16 g_w1lo[(size_t)TD * DMODEL];
__device__ __nv_bfloat16 g_w2hi[(size_t)DMODEL * DMODEL]; // W_out^T [1024,1024]
__device__ __nv_bfloat16 g_w2lo[(size_t)DMODEL * DMODEL];
__device__ __nv_bfloat16 g_ohi[(size_t)MTOT * DMODEL];    // attn out hi/lo
__device__ __nv_bfloat16 g_olo[(size_t)MTOT * DMODEL];

// ---------------------------------------------------------------------------
// mma.sync / ldmatrix helpers (sm_80+ PTX — works on plain sm_103 target)
// ---------------------------------------------------------------------------
__device__ __forceinline__ void cpasync16(uint32_t dst, const void* src) {
    asm volatile("cp.async.cg.shared.global [%0], [%1], 16;" :: "r"(dst), "l"(src));
}
__device__ __forceinline__ void ldsm_x4(uint32_t* r, uint32_t addr) {
    asm volatile("ldmatrix.sync.aligned.m8n8.x4.shared.b16 {%0,%1,%2,%3}, [%4];"
                 : "=r"(r[0]), "=r"(r[1]), "=r"(r[2]), "=r"(r[3]) : "r"(addr));
}
__device__ __forceinline__ void ldsm_x2(uint32_t* r, uint32_t addr) {
    asm volatile("ldmatrix.sync.aligned.m8n8.x2.shared.b16 {%0,%1}, [%2];"
                 : "=r"(r[0]), "=r"(r[1]) : "r"(addr));
}
__device__ __forceinline__ void ldsm_x4t(uint32_t* r, uint32_t addr) {
    asm volatile("ldmatrix.sync.aligned.m8n8.x4.trans.shared.b16 {%0,%1,%2,%3}, [%4];"
                 : "=r"(r[0]), "=r"(r[1]), "=r"(r[2]), "=r"(r[3]) : "r"(addr));
}
__device__ __forceinline__ void mma_bf16(float* d, const uint32_t* a, const uint32_t* b) {
    asm volatile("mma.sync.aligned.m16n8k16.row.col.f32.bf16.bf16.f32 "
                 "{%0,%1,%2,%3}, {%4,%5,%6,%7}, {%8,%9}, {%0,%1,%2,%3};"
                 : "+f"(d[0]), "+f"(d[1]), "+f"(d[2]), "+f"(d[3])
                 : "r"(a[0]), "r"(a[1]), "r"(a[2]), "r"(a[3]),
                   "r"(b[0]), "r"(b[1]));
}
// pack two fp32 into bf16x2 hi + bf16x2 lo (residual)
__device__ __forceinline__ void packsplit(float v0, float v1, uint32_t& hi, uint32_t& lo) {
    __nv_bfloat162 hp = __float22bfloat162_rn(make_float2(v0, v1));
    hi = *reinterpret_cast<uint32_t*>(&hp);
    __nv_bfloat162 lp = __float22bfloat162_rn(make_float2(
        v0 - __bfloat162float(hp.x), v1 - __bfloat162float(hp.y)));
    lo = *reinterpret_cast<uint32_t*>(&lp);
}

// ---------------------------------------------------------------------------
// Split / transpose conversion kernels
// ---------------------------------------------------------------------------
__global__ __launch_bounds__(256) void split_fp32_kernel(
    const float4* __restrict__ in, __nv_bfloat162* __restrict__ hi,
    __nv_bfloat162* __restrict__ lo, int n4)
{
    int i = blockIdx.x * 256 + threadIdx.x;
    if (i >= n4) return;
    float4 v = in[i];
    uint32_t h0, l0, h1, l1;
    packsplit(v.x, v.y, h0, l0);
    packsplit(v.z, v.w, h1, l1);
    ((uint32_t*)hi)[2*i] = h0; ((uint32_t*)hi)[2*i+1] = h1;
    ((uint32_t*)lo)[2*i] = l0; ((uint32_t*)lo)[2*i+1] = l1;
}

// W[K,N] fp32 -> Bop[N,K] bf16 hi/lo (transpose + split)
__global__ __launch_bounds__(256) void transpose_split_kernel(
    const float* __restrict__ W, __nv_bfloat16* __restrict__ bhi,
    __nv_bfloat16* __restrict__ blo, int K, int N)
{
    __shared__ float t[32][33];
    int nb = blockIdx.x * 32, kb = blockIdx.y * 32;
    int tx = threadIdx.x & 31, ty = threadIdx.x >> 5;
#pragma unroll
    for (int i = 0; i < 4; ++i)
        t[ty + i * 8][tx] = W[(size_t)(kb + ty + i * 8) * N + nb + tx];
    __syncthreads();
#pragma unroll
    for (int i = 0; i < 4; ++i) {
        int n = nb + ty + i * 8;
        int k = kb + tx;
        float v = t[tx][ty + i * 8];
        __nv_bfloat16 h = __float2bfloat16(v);
        bhi[(size_t)n * K + k] = h;
        blo[(size_t)n * K + k] = __float2bfloat16(v - __bfloat162float(h));
    }
}

// ---------------------------------------------------------------------------
// bf16x3 HMMA GEMM: C = A @ Bop^T + bias. 128x128 tile, BK=32, 8 warps (2x4),
// double-buffered cp.async. Output either fp32 (C) or bf16 hi/lo (Chi/Clo).
// ---------------------------------------------------------------------------
#define PITCHB 80
#define TILEB (128 * PITCHB)
#define STAGEB (4 * TILEB)
#define GSMEM (2 * STAGEB)              // 81920

__device__ __forceinline__ void g_load_chunk(uint32_t stage,
    const __nv_bfloat16* __restrict__ Ahi, const __nv_bfloat16* __restrict__ Alo,
    const __nv_bfloat16* __restrict__ Bhi, const __nv_bfloat16* __restrict__ Blo,
    int m0, int n0, int kc, int K, int tid)
{
#pragma unroll
    for (int t = 0; t < 8; ++t) {
        int tile = t >> 1;
        int idx = ((t & 1) << 8) + tid;
        int row = idx >> 2;
        int seg = idx & 3;
        uint32_t dst = stage + tile * TILEB + row * PITCHB + (seg << 4);
        size_t koff = (size_t)kc + (seg << 3);
        const __nv_bfloat16* src;
        if (tile == 0)      src = Ahi + (size_t)(m0 + row) * K + koff;
        else if (tile == 1) src = Alo + (size_t)(m0 + row) * K + koff;
        else if (tile == 2) src = Bhi + (size_t)(n0 + row) * K + koff;
        else                src = Blo + (size_t)(n0 + row) * K + koff;
        cpasync16(dst, src);
    }
}

__global__ __launch_bounds__(256, 2) void gemm_bf16x3(
    const __nv_bfloat16* __restrict__ Ahi, const __nv_bfloat16* __restrict__ Alo,
    const __nv_bfloat16* __restrict__ Bhi, const __nv_bfloat16* __restrict__ Blo,
    const float* __restrict__ bias, float* __restrict__ C,
    __nv_bfloat16* __restrict__ Chi, __nv_bfloat16* __restrict__ Clo,
    int bf16out, int M, int N, int K)
{
    extern __shared__ char smem[];
    const uint32_t sbase = (uint32_t)__cvta_generic_to_shared(smem);

    const int tid  = threadIdx.x;
    const int wid  = tid >> 5;
    const int lane = tid & 31;
    const int wm   = wid >> 2;
    const int wn   = wid & 3;
    const int m0 = blockIdx.y * 128;
    const int n0 = blockIdx.x * 128;
    const int NC = K >> 5;

    float acc[4][4][4];
#pragma unroll
    for (int i = 0; i < 4; ++i)
#pragma unroll
        for (int j = 0; j < 4; ++j)
#pragma unroll
            for (int c = 0; c < 4; ++c) acc[i][j][c] = 0.0f;

    const uint32_t a_row = (uint32_t)(wm * 64 + (lane & 15)) * PITCHB + ((lane >> 4) << 4);
    const uint32_t b_row = (uint32_t)(wn * 32 + (lane & 7)) * PITCHB + (((lane >> 3) & 1) << 4);

    g_load_chunk(sbase, Ahi, Alo, Bhi, Blo, m0, n0, 0, K, tid);
    asm volatile("cp.async.commit_group;");

    for (int k0 = 0; k0 < NC; ++k0) {
        uint32_t buf = (uint32_t)(k0 & 1) * STAGEB;
        if (k0 + 1 < NC) {
            g_load_chunk(sbase + (uint32_t)((k0 + 1) & 1) * STAGEB,
                         Ahi, Alo, Bhi, Blo, m0, n0, (k0 + 1) << 5, K, tid);
            asm volatile("cp.async.commit_group;");
            asm volatile("cp.async.wait_group 1;");
        } else {
            asm volatile("cp.async.wait_group 0;");
        }
        __syncthreads();

        const uint32_t sAhi = sbase + buf;
        const uint32_t sAlo = sAhi + TILEB;
        const uint32_t sBhi = sAlo + TILEB;
        const uint32_t sBlo = sBhi + TILEB;

#pragma unroll
        for (int kk = 0; kk < 2; ++kk) {
            const uint32_t kb = kk << 5;
            uint32_t ah[4][4], al[4][4], bh[4][2], bl[4][2];
#pragma unroll
            for (int mi = 0; mi < 4; ++mi) {
                uint32_t off = a_row + (uint32_t)(mi * 16) * PITCHB + kb;
                ldsm_x4(ah[mi], sAhi + off);
                ldsm_x4(al[mi], sAlo + off);
            }
#pragma unroll
            for (int ni = 0; ni < 4; ++ni) {
                uint32_t off = b_row + (uint32_t)(ni * 8) * PITCHB + kb;
                ldsm_x2(bh[ni], sBhi + off);
                ldsm_x2(bl[ni], sBlo + off);
            }
#pragma unroll
            for (int mi = 0; mi < 4; ++mi)
#pragma unroll
                for (int ni = 0; ni < 4; ++ni) {
                    mma_bf16(acc[mi][ni], ah[mi], bh[ni]);
                    mma_bf16(acc[mi][ni], ah[mi], bl[ni]);
                    mma_bf16(acc[mi][ni], al[mi], bh[ni]);
                }
        }
        __syncthreads();
    }

    const int rbase = m0 + wm * 64 + (lane >> 2);
    const int cbase = n0 + wn * 32 + ((lane & 3) << 1);
#pragma unroll
    for (int mi = 0; mi < 4; ++mi)
#pragma unroll
        for (int ni = 0; ni < 4; ++ni) {
            int r = rbase + mi * 16;
            int c = cbase + ni * 8;
            float b0 = bias[c], b1 = bias[c + 1];
            float v0 = acc[mi][ni][0] + b0, v1 = acc[mi][ni][1] + b1;
            float v2 = acc[mi][ni][2] + b0, v3 = acc[mi][ni][3] + b1;
            if (!bf16out) {
                *(float2*)(C + (size_t)r * N + c)       = make_float2(v0, v1);
                *(float2*)(C + (size_t)(r + 8) * N + c) = make_float2(v2, v3);
            } else {
                uint32_t h, l;
                packsplit(v0, v1, h, l);
                *(uint32_t*)(Chi + (size_t)r * N + c) = h;
                *(uint32_t*)(Clo + (size_t)r * N + c) = l;
                packsplit(v2, v3, h, l);
                *(uint32_t*)(Chi + (size_t)(r + 8) * N + c) = h;
                *(uint32_t*)(Clo + (size_t)(r + 8) * N + c) = l;
            }
        }
}

// ---------------------------------------------------------------------------
// Flash attention via HMMA bf16x3.  CTA = 128 q-rows x (64-wide K/V tiles),
// 8 warps, each warp owns 16 q rows.  Q/K/V consumed as bf16 hi/lo splits
// from GEMM1's output; P->A fragment conversion stays in registers.
// Output written bf16 hi/lo in [B,H,S,hd] order.
// ---------------------------------------------------------------------------
#define APITCH 144                       // 64 bf16 = 128B + 16B pad
#define SQHI 0
#define SQLO 18432
#define SKHI 36864
#define SKLO 46080
#define SVHI 55296
#define SVLO 64512
#define ASMEM 73728

__global__ __launch_bounds__(256, 2) void attn_flash_hmma(
    const __nv_bfloat16* __restrict__ qkvhi, const __nv_bfloat16* __restrict__ qkvlo,
    __nv_bfloat16* __restrict__ ohi, __nv_bfloat16* __restrict__ olo,
    const int* __restrict__ maskp)
{
    extern __shared__ char smemc[];
    const uint32_t sb = (uint32_t)__cvta_generic_to_shared(smemc);

    const int qt = (int)(gridDim.x - 1 - blockIdx.x);   // big tiles first
    const int h  = blockIdx.y;
    const int b  = blockIdx.z;
    const int tid  = threadIdx.x;
    const int wid  = tid >> 5;
    const int lane = tid & 31;
    const int use_mask = (maskp[0] != 0);

    const size_t base = (size_t)b * SEQ * TD + (size_t)h * (3 * HDIM);

    // ---- load Q tile (128 rows x 64) hi+lo ----
#pragma unroll
    for (int t = 0; t < 8; ++t) {
        int idx = t * 256 + tid;             // 0..2047
        int arr = idx >> 10;                 // 0 hi, 1 lo
        int rem = idx & 1023;
        int r = rem >> 3, seg = rem & 7;
        const __nv_bfloat16* src = (arr ? qkvlo : qkvhi)
            + base + (size_t)(qt * 128 + r) * TD + seg * 8;
        cpasync16(sb + (arr ? SQLO : SQHI) + r * APITCH + seg * 16, src);
    }
    asm volatile("cp.async.commit_group;");

    float oacc[8][4];
    float m0 = -INFINITY, m1 = -INFINITY, l0 = 0.0f, l1 = 0.0f;
#pragma unroll
    for (int i = 0; i < 8; ++i)
#pragma unroll
        for (int c = 0; c < 4; ++c) oacc[i][c] = 0.0f;

    const int nkt = use_mask ? (2 * qt + 2) : (SEQ / 64);

    for (int kt = 0; kt < nkt; ++kt) {
        // ---- load K,V tiles (64 rows x 64) hi+lo ----
#pragma unroll
        for (int t = 0; t < 8; ++t) {
            int idx = t * 256 + tid;         // 0..2047
            int half = idx >> 10;            // 0 K, 1 V
            int rem = idx & 1023;
            int arr = rem >> 9;              // 0 hi, 1 lo
            int rem2 = rem & 511;
            int r = rem2 >> 3, seg = rem2 & 7;
            const __nv_bfloat16* src = (arr ? qkvlo : qkvhi)
                + base + (size_t)(kt * 64 + r) * TD + 64 + half * 64 + seg * 8;
            cpasync16(sb + SKHI + half * 18432 + arr * 9216 + r * APITCH + seg * 16, src);
        }
        asm volatile("cp.async.commit_group;");
        asm volatile("cp.async.wait_group 0;");
        __syncthreads();

        // ===== scores: warp rows wid*16..+15 x 64 kt cols =====
        float sacc[8][4];
#pragma unroll
        for (int i = 0; i < 8; ++i)
#pragma unroll
            for (int c = 0; c < 4; ++c) sacc[i][c] = 0.0f;

#pragma unroll
        for (int ks = 0; ks < 4; ++ks) {
            uint32_t ah[4], alr[4];
            uint32_t qoff = (uint32_t)(wid * 16 + (lane & 15)) * APITCH
                          + ((lane >> 4) << 4) + ks * 32;
            ldsm_x4(ah,  sb + SQHI + qoff);
            ldsm_x4(alr, sb + SQLO + qoff);
#pragma unroll
            for (int nt = 0; nt < 8; ++nt) {
                uint32_t bh[2], bl[2];
                uint32_t koff = (uint32_t)(nt * 8 + (lane & 7)) * APITCH
                              + (((lane >> 3) & 1) << 4) + ks * 32;
                ldsm_x2(bh, sb + SKHI + koff);
                ldsm_x2(bl, sb + SKLO + koff);
                mma_bf16(sacc[nt], ah,  bh);
                mma_bf16(sacc[nt], ah,  bl);
                mma_bf16(sacc[nt], alr, bh);
            }
        }

        // ===== scale + mask =====
        const int row0 = qt * 128 + wid * 16 + (lane >> 2);
        const int needmask = use_mask && (kt * 64 + 63 > row0);
#pragma unroll
        for (int nt = 0; nt < 8; ++nt) {
#pragma unroll
            for (int c = 0; c < 4; ++c) sacc[nt][c] *= 0.125f;
            if (needmask) {
                int col = kt * 64 + nt * 8 + ((lane & 3) << 1);
                if (col     > row0)     sacc[nt][0] = NEG_BIG;
                if (col + 1 > row0)     sacc[nt][1] = NEG_BIG;
                if (col     > row0 + 8) sacc[nt][2] = NEG_BIG;
                if (col + 1 > row0 + 8) sacc[nt][3] = NEG_BIG;
            }
        }

        // ===== online softmax =====
        float mn0 = m0, mn1 = m1;
#pragma unroll
        for (int nt = 0; nt < 8; ++nt) {
            mn0 = fmaxf(mn0, fmaxf(sacc[nt][0], sacc[nt][1]));
            mn1 = fmaxf(mn1, fmaxf(sacc[nt][2], sacc[nt][3]));
        }
        mn0 = fmaxf(mn0, __shfl_xor_sync(0xffffffffu, mn0, 1));
        mn0 = fmaxf(mn0, __shfl_xor_sync(0xffffffffu, mn0, 2));
        mn1 = fmaxf(mn1, __shfl_xor_sync(0xffffffffu, mn1, 1));
        mn1 = fmaxf(mn1, __shfl_xor_sync(0xffffffffu, mn1, 2));
        float alpha0 = __expf(m0 - mn0);
        float alpha1 = __expf(m1 - mn1);
        m0 = mn0; m1 = mn1;

        float ls0 = 0.0f, ls1 = 0.0f;
#pragma unroll
        for (int nt = 0; nt < 8; ++nt) {
            sacc[nt][0] = __expf(sacc[nt][0] - mn0);
            sacc[nt][1] = __expf(sacc[nt][1] - mn0);
            sacc[nt][2] = __expf(sacc[nt][2] - mn1);
            sacc[nt][3] = __expf(sacc[nt][3] - mn1);
            ls0 += sacc[nt][0] + sacc[nt][1];
            ls1 += sacc[nt][2] + sacc[nt][3];
        }
        ls0 += __shfl_xor_sync(0xffffffffu, ls0, 1);
        ls0 += __shfl_xor_sync(0xffffffffu, ls0, 2);
        ls1 += __shfl_xor_sync(0xffffffffu, ls1, 1);
        ls1 += __shfl_xor_sync(0xffffffffu, ls1, 2);
        l0 = l0 * alpha0 + ls0;
        l1 = l1 * alpha1 + ls1;
#pragma unroll
        for (int nt = 0; nt < 8; ++nt) {
            oacc[nt][0] *= alpha0; oacc[nt][1] *= alpha0;
            oacc[nt][2] *= alpha1; oacc[nt][3] *= alpha1;
        }

        // ===== O += P @ V  (P fragments built in-register) =====
#pragma unroll
        for (int t = 0; t < 4; ++t) {
            uint32_t ap[4], apl[4];
            packsplit(sacc[2*t][0],   sacc[2*t][1],   ap[0], apl[0]);
            packsplit(sacc[2*t][2],   sacc[2*t][3],   ap[1], apl[1]);
            packsplit(sacc[2*t+1][0], sacc[2*t+1][1], ap[2], apl[2]);
            packsplit(sacc[2*t+1][2], sacc[2*t+1][3], ap[3], apl[3]);
#pragma unroll
            for (int nt2 = 0; nt2 < 4; ++nt2) {
                uint32_t bv[4], bvl[4];
                uint32_t voff = (uint32_t)(t * 16 + (lane & 15)) * APITCH
                              + ((lane >> 4) << 4) + nt2 * 32;
                ldsm_x4t(bv,  sb + SVHI + voff);
                ldsm_x4t(bvl, sb + SVLO + voff);
                mma_bf16(oacc[2*nt2],     ap,  bv);
                mma_bf16(oacc[2*nt2],     ap,  bvl);
                mma_bf16(oacc[2*nt2],     apl, bv);
                mma_bf16(oacc[2*nt2+1],   ap,  bv + 2);
                mma_bf16(oacc[2*nt2+1],   ap,  bvl + 2);
                mma_bf16(oacc[2*nt2+1],   apl, bv + 2);
            }
        }
        __syncthreads();
    }

    // ===== epilogue: normalize, bf16 hi/lo, [B,H,S,hd] =====
    float il0 = 1.0f / l0, il1 = 1.0f / l1;
    const size_t rb = ((size_t)(b * NHEAD + h) * SEQ + qt * 128 + wid * 16);
    const int r0 = lane >> 2, c0 = (lane & 3) << 1;
#pragma unroll
    for (int nt = 0; nt < 8; ++nt) {
        uint32_t hv, lv;
        size_t p0 = (rb + r0) * HDIM + nt * 8 + c0;
        packsplit(oacc[nt][0] * il0, oacc[nt][1] * il0, hv, lv);
        *(uint32_t*)(ohi + p0) = hv;
        *(uint32_t*)(olo + p0) = lv;
        size_t p1 = (rb + r0 + 8) * HDIM + nt * 8 + c0;
        packsplit(oacc[nt][2] * il1, oacc[nt][3] * il1, hv, lv);
        *(uint32_t*)(ohi + p1) = hv;
        *(uint32_t*)(olo + p1) = lv;
    }
}

// ---------------------------------------------------------------------------
// Launch
// ---------------------------------------------------------------------------
extern "C" void kernel_launch(void* const* d_in, const int* in_sizes, int n_in,
                              void* d_out, int out_size)
{
    const float* x     = (const float*)d_in[0];
    const float* W_qkv = (const float*)d_in[1];
    const float* b_qkv = (const float*)d_in[2];
    const float* W_out = (const float*)d_in[3];
    const float* b_out = (const float*)d_in[4];
    const int*   maskp = (const int*)d_in[5];
    float* outp = (float*)d_out;

    __nv_bfloat16 *qkvhi, *qkvlo, *xhi, *xlo, *w1hi, *w1lo, *w2hi, *w2lo, *ohi, *olo;
    cudaGetSymbolAddress((void**)&qkvhi, g_qkvhi);
    cudaGetSymbolAddress((void**)&qkvlo, g_qkvlo);
    cudaGetSymbolAddress((void**)&xhi,  g_xhi);
    cudaGetSymbolAddress((void**)&xlo,  g_xlo);
    cudaGetSymbolAddress((void**)&w1hi, g_w1hi);
    cudaGetSymbolAddress((void**)&w1lo, g_w1lo);
    cudaGetSymbolAddress((void**)&w2hi, g_w2hi);
    cudaGetSymbolAddress((void**)&w2lo, g_w2lo);
    cudaGetSymbolAddress((void**)&ohi,  g_ohi);
    cudaGetSymbolAddress((void**)&olo,  g_olo);

    cudaFuncSetAttribute(gemm_bf16x3,
                         cudaFuncAttributeMaxDynamicSharedMemorySize, GSMEM);
    cudaFuncSetAttribute(gemm_bf16x3,
                         cudaFuncAttributePreferredSharedMemoryCarveout, 100);
    cudaFuncSetAttribute(attn_flash_hmma,
                         cudaFuncAttributeMaxDynamicSharedMemorySize, ASMEM);
    cudaFuncSetAttribute(attn_flash_hmma,
                         cudaFuncAttributePreferredSharedMemoryCarveout, 100);

    // 1) split x -> bf16 hi/lo
    {
        int n4 = MTOT * DMODEL / 4;
        split_fp32_kernel<<<(n4 + 255) / 256, 256>>>(
            (const float4*)x, (__nv_bfloat162*)xhi, (__nv_bfloat162*)xlo, n4);
    }
    // 2) transpose+split weights
    {
        dim3 g1(TD / 32, DMODEL / 32);
        transpose_split_kernel<<<g1, 256>>>(W_qkv, w1hi, w1lo, DMODEL, TD);
        dim3 g2(DMODEL / 32, DMODEL / 32);
        transpose_split_kernel<<<g2, 256>>>(W_out, w2hi, w2lo, DMODEL, DMODEL);
    }
    // 3) QKV projection -> bf16 hi/lo qkv directly
    {
        dim3 grid(TD / 128, MTOT / 128);
        gemm_bf16x3<<<grid, 256, GSMEM>>>(xhi, xlo, w1hi, w1lo, b_qkv,
                                          nullptr, qkvhi, qkvlo, 1,
                                          MTOT, TD, DMODEL);
    }
    // 4) flash attention (HMMA bf16x3)
    {
        dim3 grid(SEQ / 128, NHEAD, BATCH);
        attn_flash_hmma<<<grid, 256, ASMEM>>>(qkvhi, qkvlo, ohi, olo, maskp);
    }
    // 5) output projection -> fp32 final
    {
        dim3 grid(DMODEL / 128, MTOT / 128);
        gemm_bf16x3<<<grid, 256, GSMEM>>>(ohi, olo, w2hi, w2lo, b_out,
                                          outp, nullptr, nullptr, 0,
                                          MTOT, DMODEL, DMODEL);
    }
}

// round 6
// speedup vs baseline: 3.2250x; 1.1460x over previous
#include <cuda_runtime.h>
#include <cuda_bf16.h>
#include <cstdint>

// ---------------------------------------------------------------------------
// Problem constants: B=4, S=2048, D=1024, H=16, hd=64, causal mask
// ---------------------------------------------------------------------------
#define BATCH 4
#define SEQ   2048
#define DMODEL 1024
#define NHEAD 16
#define HDIM  64
#define TD    (3 * DMODEL)          // 3072
#define MTOT  (BATCH * SEQ)         // 8192
#define NEG_BIG -1e30f

// Scratch (__device__ globals — allocation-free rule)
__device__ __nv_bfloat16 g_qkvhi[(size_t)MTOT * TD];
__device__ __nv_bfloat16 g_qkvlo[(size_t)MTOT * TD];
__device__ __nv_bfloat16 g_xhi[(size_t)MTOT * DMODEL];
__device__ __nv_bfloat16 g_xlo[(size_t)MTOT * DMODEL];
__device__ __nv_bfloat16 g_w1hi[(size_t)TD * DMODEL];
__device__ __nv_bfloat16 g_w1lo[(size_t)TD * DMODEL];
__device__ __nv_bfloat16 g_w2hi[(size_t)DMODEL * DMODEL];
__device__ __nv_bfloat16 g_w2lo[(size_t)DMODEL * DMODEL];
__device__ __nv_bfloat16 g_ohi[(size_t)MTOT * DMODEL];
__device__ __nv_bfloat16 g_olo[(size_t)MTOT * DMODEL];

// ---------------------------------------------------------------------------
// helpers
// ---------------------------------------------------------------------------
__device__ __forceinline__ void cpasync16(uint32_t dst, const void* src) {
    asm volatile("cp.async.cg.shared.global [%0], [%1], 16;" :: "r"(dst), "l"(src));
}
__device__ __forceinline__ void ldsm_x4(uint32_t* r, uint32_t addr) {
    asm volatile("ldmatrix.sync.aligned.m8n8.x4.shared.b16 {%0,%1,%2,%3}, [%4];"
                 : "=r"(r[0]), "=r"(r[1]), "=r"(r[2]), "=r"(r[3]) : "r"(addr));
}
__device__ __forceinline__ void ldsm_x4t(uint32_t* r, uint32_t addr) {
    asm volatile("ldmatrix.sync.aligned.m8n8.x4.trans.shared.b16 {%0,%1,%2,%3}, [%4];"
                 : "=r"(r[0]), "=r"(r[1]), "=r"(r[2]), "=r"(r[3]) : "r"(addr));
}
__device__ __forceinline__ void mma_bf16(float* d, const uint32_t* a, const uint32_t* b) {
    asm volatile("mma.sync.aligned.m16n8k16.row.col.f32.bf16.bf16.f32 "
                 "{%0,%1,%2,%3}, {%4,%5,%6,%7}, {%8,%9}, {%0,%1,%2,%3};"
                 : "+f"(d[0]), "+f"(d[1]), "+f"(d[2]), "+f"(d[3])
                 : "r"(a[0]), "r"(a[1]), "r"(a[2]), "r"(a[3]),
                   "r"(b[0]), "r"(b[1]));
}
__device__ __forceinline__ void packsplit(float v0, float v1, uint32_t& hi, uint32_t& lo) {
    __nv_bfloat162 hp = __float22bfloat162_rn(make_float2(v0, v1));
    hi = *reinterpret_cast<uint32_t*>(&hp);
    __nv_bfloat162 lp = __float22bfloat162_rn(make_float2(
        v0 - __bfloat162float(hp.x), v1 - __bfloat162float(hp.y)));
    lo = *reinterpret_cast<uint32_t*>(&lp);
}
// 64B rows (GEMM, BK=32), 4 granules of 16B
__device__ __forceinline__ uint32_t swz(int row, int gran) {
    return (uint32_t)(row * 64 + ((gran ^ ((row >> 1) & 3)) << 4));
}
// 128B rows (attention, hd=64), 8 granules of 16B
__device__ __forceinline__ uint32_t swz128(int row, int gran) {
    return (uint32_t)(row * 128 + ((gran ^ (row & 7)) << 4));
}

// ---------------------------------------------------------------------------
// Split / transpose conversion kernels
// ---------------------------------------------------------------------------
__global__ __launch_bounds__(256) void split_fp32_kernel(
    const float4* __restrict__ in, __nv_bfloat162* __restrict__ hi,
    __nv_bfloat162* __restrict__ lo, int n4)
{
    int i = blockIdx.x * 256 + threadIdx.x;
    if (i >= n4) return;
    float4 v = in[i];
    uint32_t h0, l0, h1, l1;
    packsplit(v.x, v.y, h0, l0);
    packsplit(v.z, v.w, h1, l1);
    ((uint32_t*)hi)[2*i] = h0; ((uint32_t*)hi)[2*i+1] = h1;
    ((uint32_t*)lo)[2*i] = l0; ((uint32_t*)lo)[2*i+1] = l1;
}

__global__ __launch_bounds__(256) void transpose_split_kernel(
    const float* __restrict__ W, __nv_bfloat16* __restrict__ bhi,
    __nv_bfloat16* __restrict__ blo, int K, int N)
{
    __shared__ float t[32][33];
    int nb = blockIdx.x * 32, kb = blockIdx.y * 32;
    int tx = threadIdx.x & 31, ty = threadIdx.x >> 5;
#pragma unroll
    for (int i = 0; i < 4; ++i)
        t[ty + i * 8][tx] = W[(size_t)(kb + ty + i * 8) * N + nb + tx];
    __syncthreads();
#pragma unroll
    for (int i = 0; i < 4; ++i) {
        int n = nb + ty + i * 8;
        int k = kb + tx;
        float v = t[tx][ty + i * 8];
        __nv_bfloat16 h = __float2bfloat16(v);
        bhi[(size_t)n * K + k] = h;
        blo[(size_t)n * K + k] = __float2bfloat16(v - __bfloat162float(h));
    }
}

// ---------------------------------------------------------------------------
// bf16x3 HMMA GEMM: 128x128 tile, BK=32, 8 warps (2x4), 3-stage cp.async,
// one __syncthreads per chunk.  Swizzled 64B-pitch smem tiles.
// ---------------------------------------------------------------------------
#define GT  8192                        // 128 rows x 64B
#define GSTAGE (4 * GT)                 // Ahi|Alo|Bhi|Blo = 32768
#define GSMEM (3 * GSTAGE)              // 98304

__device__ __forceinline__ void g_load_chunk(uint32_t stage,
    const __nv_bfloat16* __restrict__ Ahi, const __nv_bfloat16* __restrict__ Alo,
    const __nv_bfloat16* __restrict__ Bhi, const __nv_bfloat16* __restrict__ Blo,
    int m0, int n0, int kc, int K, int tid)
{
#pragma unroll
    for (int t = 0; t < 8; ++t) {
        int idx = t * 256 + tid;             // 0..2047
        int tile = idx >> 9;                 // 0..3
        int rem = idx & 511;
        int row = rem >> 2, s = rem & 3;
        uint32_t dst = stage + tile * GT + swz(row, s);
        size_t koff = (size_t)kc + (s << 3);
        const __nv_bfloat16* src;
        if (tile == 0)      src = Ahi + (size_t)(m0 + row) * K + koff;
        else if (tile == 1) src = Alo + (size_t)(m0 + row) * K + koff;
        else if (tile == 2) src = Bhi + (size_t)(n0 + row) * K + koff;
        else                src = Blo + (size_t)(n0 + row) * K + koff;
        cpasync16(dst, src);
    }
}

__global__ __launch_bounds__(256, 2) void gemm_bf16x3(
    const __nv_bfloat16* __restrict__ Ahi, const __nv_bfloat16* __restrict__ Alo,
    const __nv_bfloat16* __restrict__ Bhi, const __nv_bfloat16* __restrict__ Blo,
    const float* __restrict__ bias, float* __restrict__ C,
    __nv_bfloat16* __restrict__ Chi, __nv_bfloat16* __restrict__ Clo,
    int bf16out, int M, int N, int K)
{
    extern __shared__ char smem[];
    const uint32_t sbase = (uint32_t)__cvta_generic_to_shared(smem);

    const int tid  = threadIdx.x;
    const int wid  = tid >> 5;
    const int lane = tid & 31;
    const int wm   = wid >> 2;
    const int wn   = wid & 3;
    const int m0 = blockIdx.y * 128;
    const int n0 = blockIdx.x * 128;
    const int NC = K >> 5;

    float acc[4][4][4];
#pragma unroll
    for (int i = 0; i < 4; ++i)
#pragma unroll
        for (int j = 0; j < 4; ++j)
#pragma unroll
            for (int c = 0; c < 4; ++c) acc[i][j][c] = 0.0f;

    g_load_chunk(sbase,          Ahi, Alo, Bhi, Blo, m0, n0, 0,  K, tid);
    asm volatile("cp.async.commit_group;");
    g_load_chunk(sbase + GSTAGE, Ahi, Alo, Bhi, Blo, m0, n0, 32, K, tid);
    asm volatile("cp.async.commit_group;");

    for (int k0 = 0; k0 < NC; ++k0) {
        if (k0 + 1 < NC) asm volatile("cp.async.wait_group 1;");
        else             asm volatile("cp.async.wait_group 0;");
        __syncthreads();
        if (k0 + 2 < NC) {
            g_load_chunk(sbase + (uint32_t)((k0 + 2) % 3) * GSTAGE,
                         Ahi, Alo, Bhi, Blo, m0, n0, (k0 + 2) << 5, K, tid);
            asm volatile("cp.async.commit_group;");
        }

        const uint32_t st = sbase + (uint32_t)(k0 % 3) * GSTAGE;
        const uint32_t sAhi = st, sAlo = st + GT, sBhi = st + 2*GT, sBlo = st + 3*GT;

#pragma unroll
        for (int kk = 0; kk < 2; ++kk) {
            uint32_t ah[4][4], al[4][4], bh[2][4], bl[2][4];
#pragma unroll
            for (int mi = 0; mi < 4; ++mi) {
                int row = wm * 64 + mi * 16 + (lane & 15);
                uint32_t off = swz(row, kk * 2 + (lane >> 4));
                ldsm_x4(ah[mi], sAhi + off);
                ldsm_x4(al[mi], sAlo + off);
            }
#pragma unroll
            for (int nj = 0; nj < 2; ++nj) {
                int row = wn * 32 + nj * 16 + (lane & 7) + ((lane >> 4) << 3);
                uint32_t off = swz(row, kk * 2 + ((lane >> 3) & 1));
                ldsm_x4(bh[nj], sBhi + off);
                ldsm_x4(bl[nj], sBlo + off);
            }
#pragma unroll
            for (int mi = 0; mi < 4; ++mi)
#pragma unroll
                for (int ni = 0; ni < 4; ++ni) {
                    const uint32_t* pbh = bh[ni >> 1] + (ni & 1) * 2;
                    const uint32_t* pbl = bl[ni >> 1] + (ni & 1) * 2;
                    mma_bf16(acc[mi][ni], ah[mi], pbh);
                    mma_bf16(acc[mi][ni], ah[mi], pbl);
                    mma_bf16(acc[mi][ni], al[mi], pbh);
                }
        }
    }

    const int rbase = m0 + wm * 64 + (lane >> 2);
    const int cbase = n0 + wn * 32 + ((lane & 3) << 1);
#pragma unroll
    for (int mi = 0; mi < 4; ++mi)
#pragma unroll
        for (int ni = 0; ni < 4; ++ni) {
            int r = rbase + mi * 16;
            int c = cbase + ni * 8;
            float b0 = bias[c], b1 = bias[c + 1];
            float v0 = acc[mi][ni][0] + b0, v1 = acc[mi][ni][1] + b1;
            float v2 = acc[mi][ni][2] + b0, v3 = acc[mi][ni][3] + b1;
            if (!bf16out) {
                *(float2*)(C + (size_t)r * N + c)       = make_float2(v0, v1);
                *(float2*)(C + (size_t)(r + 8) * N + c) = make_float2(v2, v3);
            } else {
                uint32_t h, l;
                packsplit(v0, v1, h, l);
                *(uint32_t*)(Chi + (size_t)r * N + c) = h;
                *(uint32_t*)(Clo + (size_t)r * N + c) = l;
                packsplit(v2, v3, h, l);
                *(uint32_t*)(Chi + (size_t)(r + 8) * N + c) = h;
                *(uint32_t*)(Clo + (size_t)(r + 8) * N + c) = l;
            }
        }
}

// ---------------------------------------------------------------------------
// Flash attention, HMMA bf16x3, double-buffered K/V, 128B-pitch swizzle.
// CTA = 128 q-rows; 8 warps, each owns 16 q-rows.
// ---------------------------------------------------------------------------
#define AQHI 0
#define AQLO 16384
#define AKV  32768           // 2 stages x 32768 (Khi|Klo|Vhi|Vlo, 8192 each)
#define AKVST 32768
#define ASMEM 98304

__global__ __launch_bounds__(256, 2) void attn_flash_hmma(
    const __nv_bfloat16* __restrict__ qkvhi, const __nv_bfloat16* __restrict__ qkvlo,
    __nv_bfloat16* __restrict__ ohi, __nv_bfloat16* __restrict__ olo,
    const int* __restrict__ maskp)
{
    extern __shared__ char smemc[];
    const uint32_t sb = (uint32_t)__cvta_generic_to_shared(smemc);

    const int qt = (int)(gridDim.x - 1 - blockIdx.x);
    const int h  = blockIdx.y;
    const int b  = blockIdx.z;
    const int tid  = threadIdx.x;
    const int wid  = tid >> 5;
    const int lane = tid & 31;
    const int use_mask = (maskp[0] != 0);

    const size_t base = (size_t)b * SEQ * TD + (size_t)h * (3 * HDIM);
    const int nkt = use_mask ? (2 * qt + 2) : (SEQ / 64);

    // ---- Q tile (128 rows x 64 bf16, hi+lo) ----
#pragma unroll
    for (int t = 0; t < 8; ++t) {
        int idx = t * 256 + tid;             // 0..2047
        int arr = idx >> 10;                 // 0 hi, 1 lo
        int rem = idx & 1023;
        int row = rem >> 3, s = rem & 7;
        const __nv_bfloat16* src = (arr ? qkvlo : qkvhi)
            + base + (size_t)(qt * 128 + row) * TD + s * 8;
        cpasync16(sb + (arr ? AQLO : AQHI) + swz128(row, s), src);
    }
    asm volatile("cp.async.commit_group;");

    // ---- K/V stage loader ----
    auto load_kv = [&](int kt) {
        uint32_t stg = sb + AKV + (uint32_t)(kt & 1) * AKVST;
#pragma unroll
        for (int t = 0; t < 8; ++t) {
            int idx = t * 256 + tid;         // 0..2047
            int tile = idx >> 9;             // 0 Khi, 1 Klo, 2 Vhi, 3 Vlo
            int rem = idx & 511;
            int row = rem >> 3, s = rem & 7;
            int dcol = (tile >> 1) ? 128 : 64;   // V at +128, K at +64
            const __nv_bfloat16* src = ((tile & 1) ? qkvlo : qkvhi)
                + base + (size_t)(kt * 64 + row) * TD + dcol + s * 8;
            cpasync16(stg + tile * 8192 + swz128(row, s), src);
        }
        asm volatile("cp.async.commit_group;");
    };

    load_kv(0);

    float oacc[8][4];
    float m0 = -INFINITY, m1 = -INFINITY, l0 = 0.0f, l1 = 0.0f;
#pragma unroll
    for (int i = 0; i < 8; ++i)
#pragma unroll
        for (int c = 0; c < 4; ++c) oacc[i][c] = 0.0f;

    for (int kt = 0; kt < nkt; ++kt) {
        asm volatile("cp.async.wait_group 0;");
        __syncthreads();
        if (kt + 1 < nkt) load_kv(kt + 1);

        const uint32_t stg = sb + AKV + (uint32_t)(kt & 1) * AKVST;
        const uint32_t sKhi = stg, sKlo = stg + 8192;
        const uint32_t sVhi = stg + 16384, sVlo = stg + 24576;

        // ===== scores =====
        float sacc[8][4];
#pragma unroll
        for (int i = 0; i < 8; ++i)
#pragma unroll
            for (int c = 0; c < 4; ++c) sacc[i][c] = 0.0f;

#pragma unroll
        for (int ks = 0; ks < 4; ++ks) {
            uint32_t ah[4], alr[4];
            {
                int row = wid * 16 + (lane & 15);
                uint32_t off = swz128(row, ks * 2 + (lane >> 4));
                ldsm_x4(ah,  sb + AQHI + off);
                ldsm_x4(alr, sb + AQLO + off);
            }
#pragma unroll
            for (int nj = 0; nj < 4; ++nj) {
                uint32_t bh[4], bl[4];
                int row = nj * 16 + (lane & 7) + ((lane >> 4) << 3);
                uint32_t off = swz128(row, ks * 2 + ((lane >> 3) & 1));
                ldsm_x4(bh, sKhi + off);
                ldsm_x4(bl, sKlo + off);
#pragma unroll
                for (int half = 0; half < 2; ++half) {
                    int nt = nj * 2 + half;
                    mma_bf16(sacc[nt], ah,  bh + half * 2);
                    mma_bf16(sacc[nt], ah,  bl + half * 2);
                    mma_bf16(sacc[nt], alr, bh + half * 2);
                }
            }
        }

        // ===== scale + mask =====
        const int row0 = qt * 128 + wid * 16 + (lane >> 2);
        const int needmask = use_mask && (kt * 64 + 63 > row0);
#pragma unroll
        for (int nt = 0; nt < 8; ++nt) {
#pragma unroll
            for (int c = 0; c < 4; ++c) sacc[nt][c] *= 0.125f;
            if (needmask) {
                int col = kt * 64 + nt * 8 + ((lane & 3) << 1);
                if (col     > row0)     sacc[nt][0] = NEG_BIG;
                if (col + 1 > row0)     sacc[nt][1] = NEG_BIG;
                if (col     > row0 + 8) sacc[nt][2] = NEG_BIG;
                if (col + 1 > row0 + 8) sacc[nt][3] = NEG_BIG;
            }
        }

        // ===== online softmax =====
        float mn0 = m0, mn1 = m1;
#pragma unroll
        for (int nt = 0; nt < 8; ++nt) {
            mn0 = fmaxf(mn0, fmaxf(sacc[nt][0], sacc[nt][1]));
            mn1 = fmaxf(mn1, fmaxf(sacc[nt][2], sacc[nt][3]));
        }
        mn0 = fmaxf(mn0, __shfl_xor_sync(0xffffffffu, mn0, 1));
        mn0 = fmaxf(mn0, __shfl_xor_sync(0xffffffffu, mn0, 2));
        mn1 = fmaxf(mn1, __shfl_xor_sync(0xffffffffu, mn1, 1));
        mn1 = fmaxf(mn1, __shfl_xor_sync(0xffffffffu, mn1, 2));
        float alpha0 = __expf(m0 - mn0);
        float alpha1 = __expf(m1 - mn1);
        m0 = mn0; m1 = mn1;

        float ls0 = 0.0f, ls1 = 0.0f;
#pragma unroll
        for (int nt = 0; nt < 8; ++nt) {
            sacc[nt][0] = __expf(sacc[nt][0] - mn0);
            sacc[nt][1] = __expf(sacc[nt][1] - mn0);
            sacc[nt][2] = __expf(sacc[nt][2] - mn1);
            sacc[nt][3] = __expf(sacc[nt][3] - mn1);
            ls0 += sacc[nt][0] + sacc[nt][1];
            ls1 += sacc[nt][2] + sacc[nt][3];
        }
        ls0 += __shfl_xor_sync(0xffffffffu, ls0, 1);
        ls0 += __shfl_xor_sync(0xffffffffu, ls0, 2);
        ls1 += __shfl_xor_sync(0xffffffffu, ls1, 1);
        ls1 += __shfl_xor_sync(0xffffffffu, ls1, 2);
        l0 = l0 * alpha0 + ls0;
        l1 = l1 * alpha1 + ls1;
#pragma unroll
        for (int nt = 0; nt < 8; ++nt) {
            oacc[nt][0] *= alpha0; oacc[nt][1] *= alpha0;
            oacc[nt][2] *= alpha1; oacc[nt][3] *= alpha1;
        }

        // ===== O += P @ V =====
#pragma unroll
        for (int t = 0; t < 4; ++t) {
            uint32_t ap[4], apl[4];
            packsplit(sacc[2*t][0],   sacc[2*t][1],   ap[0], apl[0]);
            packsplit(sacc[2*t][2],   sacc[2*t][3],   ap[1], apl[1]);
            packsplit(sacc[2*t+1][0], sacc[2*t+1][1], ap[2], apl[2]);
            packsplit(sacc[2*t+1][2], sacc[2*t+1][3], ap[3], apl[3]);
#pragma unroll
            for (int nt2 = 0; nt2 < 4; ++nt2) {
                uint32_t bv[4], bvl[4];
                int row = t * 16 + (lane & 15);
                uint32_t off = swz128(row, nt2 * 2 + (lane >> 4));
                ldsm_x4t(bv,  sVhi + off);
                ldsm_x4t(bvl, sVlo + off);
                mma_bf16(oacc[2*nt2],   ap,  bv);
                mma_bf16(oacc[2*nt2],   ap,  bvl);
                mma_bf16(oacc[2*nt2],   apl, bv);
                mma_bf16(oacc[2*nt2+1], ap,  bv + 2);
                mma_bf16(oacc[2*nt2+1], ap,  bvl + 2);
                mma_bf16(oacc[2*nt2+1], apl, bv + 2);
            }
        }
    }

    // ===== epilogue =====
    float il0 = 1.0f / l0, il1 = 1.0f / l1;
    const size_t rb = ((size_t)(b * NHEAD + h) * SEQ + qt * 128 + wid * 16);
    const int r0 = lane >> 2, c0 = (lane & 3) << 1;
#pragma unroll
    for (int nt = 0; nt < 8; ++nt) {
        uint32_t hv, lv;
        size_t p0 = (rb + r0) * HDIM + nt * 8 + c0;
        packsplit(oacc[nt][0] * il0, oacc[nt][1] * il0, hv, lv);
        *(uint32_t*)(ohi + p0) = hv;
        *(uint32_t*)(olo + p0) = lv;
        size_t p1 = (rb + r0 + 8) * HDIM + nt * 8 + c0;
        packsplit(oacc[nt][2] * il1, oacc[nt][3] * il1, hv, lv);
        *(uint32_t*)(ohi + p1) = hv;
        *(uint32_t*)(olo + p1) = lv;
    }
}

// ---------------------------------------------------------------------------
// Launch
// ---------------------------------------------------------------------------
extern "C" void kernel_launch(void* const* d_in, const int* in_sizes, int n_in,
                              void* d_out, int out_size)
{
    const float* x     = (const float*)d_in[0];
    const float* W_qkv = (const float*)d_in[1];
    const float* b_qkv = (const float*)d_in[2];
    const float* W_out = (const float*)d_in[3];
    const float* b_out = (const float*)d_in[4];
    const int*   maskp = (const int*)d_in[5];
    float* outp = (float*)d_out;

    __nv_bfloat16 *qkvhi, *qkvlo, *xhi, *xlo, *w1hi, *w1lo, *w2hi, *w2lo, *ohi, *olo;
    cudaGetSymbolAddress((void**)&qkvhi, g_qkvhi);
    cudaGetSymbolAddress((void**)&qkvlo, g_qkvlo);
    cudaGetSymbolAddress((void**)&xhi,  g_xhi);
    cudaGetSymbolAddress((void**)&xlo,  g_xlo);
    cudaGetSymbolAddress((void**)&w1hi, g_w1hi);
    cudaGetSymbolAddress((void**)&w1lo, g_w1lo);
    cudaGetSymbolAddress((void**)&w2hi, g_w2hi);
    cudaGetSymbolAddress((void**)&w2lo, g_w2lo);
    cudaGetSymbolAddress((void**)&ohi,  g_ohi);
    cudaGetSymbolAddress((void**)&olo,  g_olo);

    cudaFuncSetAttribute(gemm_bf16x3,
                         cudaFuncAttributeMaxDynamicSharedMemorySize, GSMEM);
    cudaFuncSetAttribute(gemm_bf16x3,
                         cudaFuncAttributePreferredSharedMemoryCarveout, 100);
    cudaFuncSetAttribute(attn_flash_hmma,
                         cudaFuncAttributeMaxDynamicSharedMemorySize, ASMEM);
    cudaFuncSetAttribute(attn_flash_hmma,
                         cudaFuncAttributePreferredSharedMemoryCarveout, 100);

    {
        int n4 = MTOT * DMODEL / 4;
        split_fp32_kernel<<<(n4 + 255) / 256, 256>>>(
            (const float4*)x, (__nv_bfloat162*)xhi, (__nv_bfloat162*)xlo, n4);
    }
    {
        dim3 g1(TD / 32, DMODEL / 32);
        transpose_split_kernel<<<g1, 256>>>(W_qkv, w1hi, w1lo, DMODEL, TD);
        dim3 g2(DMODEL / 32, DMODEL / 32);
        transpose_split_kernel<<<g2, 256>>>(W_out, w2hi, w2lo, DMODEL, DMODEL);
    }
    {
        dim3 grid(TD / 128, MTOT / 128);
        gemm_bf16x3<<<grid, 256, GSMEM>>>(xhi, xlo, w1hi, w1lo, b_qkv,
                                          nullptr, qkvhi, qkvlo, 1,
                                          MTOT, TD, DMODEL);
    }
    {
        dim3 grid(SEQ / 128, NHEAD, BATCH);
        attn_flash_hmma<<<grid, 256, ASMEM>>>(qkvhi, qkvlo, ohi, olo, maskp);
    }
    {
        dim3 grid(DMODEL / 128, MTOT / 128);
        gemm_bf16x3<<<grid, 256, GSMEM>>>(ohi, olo, w2hi, w2lo, b_out,
                                          outp, nullptr, nullptr, 0,
                                          MTOT, DMODEL, DMODEL);
    }
}

// round 7
// speedup vs baseline: 3.3873x; 1.0503x over previous
#include <cuda_runtime.h>
#include <cuda_bf16.h>
#include <cstdint>

// ---------------------------------------------------------------------------
// Problem constants: B=4, S=2048, D=1024, H=16, hd=64, causal mask
// ---------------------------------------------------------------------------
#define BATCH 4
#define SEQ   2048
#define DMODEL 1024
#define NHEAD 16
#define HDIM  64
#define TD    (3 * DMODEL)          // 3072
#define MTOT  (BATCH * SEQ)         // 8192
#define NEG_BIG -1e30f
#define NSM_X2 304                  // 2 CTAs x 152 SMs (GB300)

// Scratch (__device__ globals — allocation-free rule)
__device__ __nv_bfloat16 g_qkvhi[(size_t)MTOT * TD];
__device__ __nv_bfloat16 g_qkvlo[(size_t)MTOT * TD];
__device__ __nv_bfloat16 g_xhi[(size_t)MTOT * DMODEL];
__device__ __nv_bfloat16 g_xlo[(size_t)MTOT * DMODEL];
__device__ __nv_bfloat16 g_w1hi[(size_t)TD * DMODEL];
__device__ __nv_bfloat16 g_w1lo[(size_t)TD * DMODEL];
__device__ __nv_bfloat16 g_w2hi[(size_t)DMODEL * DMODEL];
__device__ __nv_bfloat16 g_w2lo[(size_t)DMODEL * DMODEL];
__device__ __nv_bfloat16 g_ohi[(size_t)MTOT * DMODEL];
__device__ __nv_bfloat16 g_olo[(size_t)MTOT * DMODEL];

// ---------------------------------------------------------------------------
// helpers
// ---------------------------------------------------------------------------
__device__ __forceinline__ void cpasync16(uint32_t dst, const void* src) {
    asm volatile("cp.async.cg.shared.global [%0], [%1], 16;" :: "r"(dst), "l"(src));
}
__device__ __forceinline__ void ldsm_x4(uint32_t* r, uint32_t addr) {
    asm volatile("ldmatrix.sync.aligned.m8n8.x4.shared.b16 {%0,%1,%2,%3}, [%4];"
                 : "=r"(r[0]), "=r"(r[1]), "=r"(r[2]), "=r"(r[3]) : "r"(addr));
}
__device__ __forceinline__ void ldsm_x4t(uint32_t* r, uint32_t addr) {
    asm volatile("ldmatrix.sync.aligned.m8n8.x4.trans.shared.b16 {%0,%1,%2,%3}, [%4];"
                 : "=r"(r[0]), "=r"(r[1]), "=r"(r[2]), "=r"(r[3]) : "r"(addr));
}
__device__ __forceinline__ void mma_bf16(float* d, const uint32_t* a, const uint32_t* b) {
    asm volatile("mma.sync.aligned.m16n8k16.row.col.f32.bf16.bf16.f32 "
                 "{%0,%1,%2,%3}, {%4,%5,%6,%7}, {%8,%9}, {%0,%1,%2,%3};"
                 : "+f"(d[0]), "+f"(d[1]), "+f"(d[2]), "+f"(d[3])
                 : "r"(a[0]), "r"(a[1]), "r"(a[2]), "r"(a[3]),
                   "r"(b[0]), "r"(b[1]));
}
__device__ __forceinline__ float ex2(float x) {
    float r;
    asm("ex2.approx.f32 %0, %1;" : "=f"(r) : "f"(x));
    return r;
}
__device__ __forceinline__ void packsplit(float v0, float v1, uint32_t& hi, uint32_t& lo) {
    __nv_bfloat162 hp = __float22bfloat162_rn(make_float2(v0, v1));
    hi = *reinterpret_cast<uint32_t*>(&hp);
    __nv_bfloat162 lp = __float22bfloat162_rn(make_float2(
        v0 - __bfloat162float(hp.x), v1 - __bfloat162float(hp.y)));
    lo = *reinterpret_cast<uint32_t*>(&lp);
}
// 64B rows (GEMM, BK=32), 4 granules of 16B
__device__ __forceinline__ uint32_t swz(int row, int gran) {
    return (uint32_t)(row * 64 + ((gran ^ ((row >> 1) & 3)) << 4));
}
// 128B rows (attention, hd=64), 8 granules of 16B
__device__ __forceinline__ uint32_t swz128(int row, int gran) {
    return (uint32_t)(row * 128 + ((gran ^ (row & 7)) << 4));
}

// ---------------------------------------------------------------------------
// Fused prep: phase 0 split x, phase 1 transpose+split W_qkv, phase 2 W_out
// ---------------------------------------------------------------------------
#define SPLIT_BLKS (MTOT * DMODEL / 4 / 256)            // 8192
#define T1_BX (TD / 32)                                 // 96
#define T1_BLKS (T1_BX * (DMODEL / 32))                 // 3072
#define T2_BX (DMODEL / 32)                             // 32
#define T2_BLKS (T2_BX * (DMODEL / 32))                 // 1024
#define PREP_BLKS (SPLIT_BLKS + T1_BLKS + T2_BLKS)

__device__ __forceinline__ void do_transpose_split(
    const float* __restrict__ W, __nv_bfloat16* __restrict__ bhi,
    __nv_bfloat16* __restrict__ blo, int K, int N, int bidx, int bx_count)
{
    __shared__ float t[32][33];
    int nb = (bidx % bx_count) * 32, kb = (bidx / bx_count) * 32;
    int tx = threadIdx.x & 31, ty = threadIdx.x >> 5;
#pragma unroll
    for (int i = 0; i < 4; ++i)
        t[ty + i * 8][tx] = W[(size_t)(kb + ty + i * 8) * N + nb + tx];
    __syncthreads();
#pragma unroll
    for (int i = 0; i < 4; ++i) {
        int n = nb + ty + i * 8;
        int k = kb + tx;
        float v = t[tx][ty + i * 8];
        __nv_bfloat16 h = __float2bfloat16(v);
        bhi[(size_t)n * K + k] = h;
        blo[(size_t)n * K + k] = __float2bfloat16(v - __bfloat162float(h));
    }
}

__global__ __launch_bounds__(256) void prep_kernel(
    const float* __restrict__ x,
    __nv_bfloat16* __restrict__ xhi, __nv_bfloat16* __restrict__ xlo,
    const float* __restrict__ W1, __nv_bfloat16* __restrict__ w1hi,
    __nv_bfloat16* __restrict__ w1lo,
    const float* __restrict__ W2, __nv_bfloat16* __restrict__ w2hi,
    __nv_bfloat16* __restrict__ w2lo)
{
    int bid = blockIdx.x;
    if (bid < SPLIT_BLKS) {
        int i = bid * 256 + threadIdx.x;
        float4 v = ((const float4*)x)[i];
        uint32_t h0, l0, h1, l1;
        packsplit(v.x, v.y, h0, l0);
        packsplit(v.z, v.w, h1, l1);
        ((uint32_t*)xhi)[2*i] = h0; ((uint32_t*)xhi)[2*i+1] = h1;
        ((uint32_t*)xlo)[2*i] = l0; ((uint32_t*)xlo)[2*i+1] = l1;
    } else if (bid < SPLIT_BLKS + T1_BLKS) {
        do_transpose_split(W1, w1hi, w1lo, DMODEL, TD, bid - SPLIT_BLKS, T1_BX);
    } else {
        do_transpose_split(W2, w2hi, w2lo, DMODEL, DMODEL,
                           bid - SPLIT_BLKS - T1_BLKS, T2_BX);
    }
}

// ---------------------------------------------------------------------------
// bf16x3 HMMA GEMM, persistent: grid-stride over 128x128 tiles.
// BK=32, 8 warps (2x4), 3-stage cp.async, one __syncthreads per chunk.
// ---------------------------------------------------------------------------
#define GT  8192                        // 128 rows x 64B
#define GSTAGE (4 * GT)                 // Ahi|Alo|Bhi|Blo = 32768
#define GSMEM (3 * GSTAGE)              // 98304

__device__ __forceinline__ void g_load_chunk(uint32_t stage,
    const __nv_bfloat16* __restrict__ Ahi, const __nv_bfloat16* __restrict__ Alo,
    const __nv_bfloat16* __restrict__ Bhi, const __nv_bfloat16* __restrict__ Blo,
    int m0, int n0, int kc, int K, int tid)
{
#pragma unroll
    for (int t = 0; t < 8; ++t) {
        int idx = t * 256 + tid;             // 0..2047
        int tile = idx >> 9;                 // 0..3
        int rem = idx & 511;
        int row = rem >> 2, s = rem & 3;
        uint32_t dst = stage + tile * GT + swz(row, s);
        size_t koff = (size_t)kc + (s << 3);
        const __nv_bfloat16* src;
        if (tile == 0)      src = Ahi + (size_t)(m0 + row) * K + koff;
        else if (tile == 1) src = Alo + (size_t)(m0 + row) * K + koff;
        else if (tile == 2) src = Bhi + (size_t)(n0 + row) * K + koff;
        else                src = Blo + (size_t)(n0 + row) * K + koff;
        cpasync16(dst, src);
    }
}

__global__ __launch_bounds__(256, 2) void gemm_bf16x3(
    const __nv_bfloat16* __restrict__ Ahi, const __nv_bfloat16* __restrict__ Alo,
    const __nv_bfloat16* __restrict__ Bhi, const __nv_bfloat16* __restrict__ Blo,
    const float* __restrict__ bias, float* __restrict__ C,
    __nv_bfloat16* __restrict__ Chi, __nv_bfloat16* __restrict__ Clo,
    int bf16out, int M, int N, int K, int NTILES, int NBX)
{
    extern __shared__ char smem[];
    const uint32_t sbase = (uint32_t)__cvta_generic_to_shared(smem);

    const int tid  = threadIdx.x;
    const int wid  = tid >> 5;
    const int lane = tid & 31;
    const int wm   = wid >> 2;
    const int wn   = wid & 3;
    const int NC = K >> 5;

    for (int tix = blockIdx.x; tix < NTILES; tix += gridDim.x) {
        const int m0 = (tix / NBX) * 128;
        const int n0 = (tix % NBX) * 128;

        __syncthreads();   // prior tile fully done with smem stages

        float acc[4][4][4];
#pragma unroll
        for (int i = 0; i < 4; ++i)
#pragma unroll
            for (int j = 0; j < 4; ++j)
#pragma unroll
                for (int c = 0; c < 4; ++c) acc[i][j][c] = 0.0f;

        g_load_chunk(sbase,          Ahi, Alo, Bhi, Blo, m0, n0, 0,  K, tid);
        asm volatile("cp.async.commit_group;");
        g_load_chunk(sbase + GSTAGE, Ahi, Alo, Bhi, Blo, m0, n0, 32, K, tid);
        asm volatile("cp.async.commit_group;");

        for (int k0 = 0; k0 < NC; ++k0) {
            if (k0 + 1 < NC) asm volatile("cp.async.wait_group 1;");
            else             asm volatile("cp.async.wait_group 0;");
            __syncthreads();
            if (k0 + 2 < NC) {
                g_load_chunk(sbase + (uint32_t)((k0 + 2) % 3) * GSTAGE,
                             Ahi, Alo, Bhi, Blo, m0, n0, (k0 + 2) << 5, K, tid);
                asm volatile("cp.async.commit_group;");
            }

            const uint32_t st = sbase + (uint32_t)(k0 % 3) * GSTAGE;
            const uint32_t sAhi = st, sAlo = st + GT,
                           sBhi = st + 2*GT, sBlo = st + 3*GT;

#pragma unroll
            for (int kk = 0; kk < 2; ++kk) {
                uint32_t ah[4][4], al[4][4], bh[2][4], bl[2][4];
#pragma unroll
                for (int mi = 0; mi < 4; ++mi) {
                    int row = wm * 64 + mi * 16 + (lane & 15);
                    uint32_t off = swz(row, kk * 2 + (lane >> 4));
                    ldsm_x4(ah[mi], sAhi + off);
                    ldsm_x4(al[mi], sAlo + off);
                }
#pragma unroll
                for (int nj = 0; nj < 2; ++nj) {
                    int row = wn * 32 + nj * 16 + (lane & 7) + ((lane >> 4) << 3);
                    uint32_t off = swz(row, kk * 2 + ((lane >> 3) & 1));
                    ldsm_x4(bh[nj], sBhi + off);
                    ldsm_x4(bl[nj], sBlo + off);
                }
#pragma unroll
                for (int mi = 0; mi < 4; ++mi)
#pragma unroll
                    for (int ni = 0; ni < 4; ++ni) {
                        const uint32_t* pbh = bh[ni >> 1] + (ni & 1) * 2;
                        const uint32_t* pbl = bl[ni >> 1] + (ni & 1) * 2;
                        mma_bf16(acc[mi][ni], ah[mi], pbh);
                        mma_bf16(acc[mi][ni], ah[mi], pbl);
                        mma_bf16(acc[mi][ni], al[mi], pbh);
                    }
            }
        }

        const int rbase = m0 + wm * 64 + (lane >> 2);
        const int cbase = n0 + wn * 32 + ((lane & 3) << 1);
#pragma unroll
        for (int mi = 0; mi < 4; ++mi)
#pragma unroll
            for (int ni = 0; ni < 4; ++ni) {
                int r = rbase + mi * 16;
                int c = cbase + ni * 8;
                float b0 = bias[c], b1 = bias[c + 1];
                float v0 = acc[mi][ni][0] + b0, v1 = acc[mi][ni][1] + b1;
                float v2 = acc[mi][ni][2] + b0, v3 = acc[mi][ni][3] + b1;
                if (!bf16out) {
                    *(float2*)(C + (size_t)r * N + c)       = make_float2(v0, v1);
                    *(float2*)(C + (size_t)(r + 8) * N + c) = make_float2(v2, v3);
                } else {
                    uint32_t h, l;
                    packsplit(v0, v1, h, l);
                    *(uint32_t*)(Chi + (size_t)r * N + c) = h;
                    *(uint32_t*)(Clo + (size_t)r * N + c) = l;
                    packsplit(v2, v3, h, l);
                    *(uint32_t*)(Chi + (size_t)(r + 8) * N + c) = h;
                    *(uint32_t*)(Clo + (size_t)(r + 8) * N + c) = l;
                }
            }
    }
}

// ---------------------------------------------------------------------------
// Flash attention, persistent boustrophedon schedule over units sorted by
// descending cost (qt desc).  HMMA bf16x3, double-buffered K/V.
// ---------------------------------------------------------------------------
#define AQHI 0
#define AQLO 16384
#define AKV  32768
#define AKVST 32768
#define ASMEM 98304
#define NUNITS ((SEQ / 128) * NHEAD * BATCH)   // 1024
#define EXSCALE (0.125f * 1.44269504f)         // 1/sqrt(64) * log2(e)

__global__ __launch_bounds__(256, 2) void attn_flash_hmma(
    const __nv_bfloat16* __restrict__ qkvhi, const __nv_bfloat16* __restrict__ qkvlo,
    __nv_bfloat16* __restrict__ ohi, __nv_bfloat16* __restrict__ olo,
    const int* __restrict__ maskp)
{
    extern __shared__ char smemc[];
    const uint32_t sb = (uint32_t)__cvta_generic_to_shared(smemc);

    const int tid  = threadIdx.x;
    const int wid  = tid >> 5;
    const int lane = tid & 31;
    const int use_mask = (maskp[0] != 0);
    const int G = (int)gridDim.x;

    for (int r = 0; ; ++r) {
        int slot = (r & 1) ? (G - 1 - (int)blockIdx.x) : (int)blockIdx.x;
        int u = r * G + slot;
        if (u >= NUNITS) break;

        const int qt = (SEQ / 128 - 1) - (u >> 6);   // sorted: big qt first
        const int b  = (u >> 4) & 3;
        const int h  = u & 15;
        const size_t base = (size_t)b * SEQ * TD + (size_t)h * (3 * HDIM);
        const int nkt = use_mask ? (2 * qt + 2) : (SEQ / 64);

        __syncthreads();   // prior unit fully done with Q/KV smem

        // ---- Q tile (128 rows x 64 bf16, hi+lo) ----
#pragma unroll
        for (int t = 0; t < 8; ++t) {
            int idx = t * 256 + tid;
            int arr = idx >> 10;
            int rem = idx & 1023;
            int row = rem >> 3, s = rem & 7;
            const __nv_bfloat16* src = (arr ? qkvlo : qkvhi)
                + base + (size_t)(qt * 128 + row) * TD + s * 8;
            cpasync16(sb + (arr ? AQLO : AQHI) + swz128(row, s), src);
        }
        asm volatile("cp.async.commit_group;");

        // ---- K/V stage loader ----
        auto load_kv = [&](int kt) {
            uint32_t stg = sb + AKV + (uint32_t)(kt & 1) * AKVST;
#pragma unroll
            for (int t = 0; t < 8; ++t) {
                int idx = t * 256 + tid;
                int tile = idx >> 9;             // Khi,Klo,Vhi,Vlo
                int rem = idx & 511;
                int row = rem >> 3, s = rem & 7;
                int dcol = (tile >> 1) ? 128 : 64;
                const __nv_bfloat16* src = ((tile & 1) ? qkvlo : qkvhi)
                    + base + (size_t)(kt * 64 + row) * TD + dcol + s * 8;
                cpasync16(stg + tile * 8192 + swz128(row, s), src);
            }
            asm volatile("cp.async.commit_group;");
        };

        load_kv(0);

        float oacc[8][4];
        float m0 = -INFINITY, m1 = -INFINITY, l0 = 0.0f, l1 = 0.0f;
#pragma unroll
        for (int i = 0; i < 8; ++i)
#pragma unroll
            for (int c = 0; c < 4; ++c) oacc[i][c] = 0.0f;

        const int row0 = qt * 128 + wid * 16 + (lane >> 2);
        const int wrow_hi = qt * 128 + wid * 16 + 15;   // warp's max q row

        for (int kt = 0; kt < nkt; ++kt) {
            asm volatile("cp.async.wait_group 0;");
            __syncthreads();
            if (kt + 1 < nkt) load_kv(kt + 1);

            // fully-masked warp-tile: every k col > every q row -> skip
            if (use_mask && (kt * 64 > wrow_hi)) continue;

            const uint32_t stg = sb + AKV + (uint32_t)(kt & 1) * AKVST;
            const uint32_t sKhi = stg, sKlo = stg + 8192;
            const uint32_t sVhi = stg + 16384, sVlo = stg + 24576;

            // ===== scores =====
            float sacc[8][4];
#pragma unroll
            for (int i = 0; i < 8; ++i)
#pragma unroll
                for (int c = 0; c < 4; ++c) sacc[i][c] = 0.0f;

#pragma unroll
            for (int ks = 0; ks < 4; ++ks) {
                uint32_t ah[4], alr[4];
                {
                    int row = wid * 16 + (lane & 15);
                    uint32_t off = swz128(row, ks * 2 + (lane >> 4));
                    ldsm_x4(ah,  sb + AQHI + off);
                    ldsm_x4(alr, sb + AQLO + off);
                }
#pragma unroll
                for (int nj = 0; nj < 4; ++nj) {
                    uint32_t bh[4], bl[4];
                    int row = nj * 16 + (lane & 7) + ((lane >> 4) << 3);
                    uint32_t off = swz128(row, ks * 2 + ((lane >> 3) & 1));
                    ldsm_x4(bh, sKhi + off);
                    ldsm_x4(bl, sKlo + off);
#pragma unroll
                    for (int half = 0; half < 2; ++half) {
                        int nt = nj * 2 + half;
                        mma_bf16(sacc[nt], ah,  bh + half * 2);
                        mma_bf16(sacc[nt], ah,  bl + half * 2);
                        mma_bf16(sacc[nt], alr, bh + half * 2);
                    }
                }
            }

            // ===== scale (exp2 domain) + mask =====
            const int needmask = use_mask && (kt * 64 + 63 > row0);
#pragma unroll
            for (int nt = 0; nt < 8; ++nt) {
#pragma unroll
                for (int c = 0; c < 4; ++c) sacc[nt][c] *= EXSCALE;
                if (needmask) {
                    int col = kt * 64 + nt * 8 + ((lane & 3) << 1);
                    if (col     > row0)     sacc[nt][0] = NEG_BIG;
                    if (col + 1 > row0)     sacc[nt][1] = NEG_BIG;
                    if (col     > row0 + 8) sacc[nt][2] = NEG_BIG;
                    if (col + 1 > row0 + 8) sacc[nt][3] = NEG_BIG;
                }
            }

            // ===== online softmax (base-2) =====
            float mn0 = m0, mn1 = m1;
#pragma unroll
            for (int nt = 0; nt < 8; ++nt) {
                mn0 = fmaxf(mn0, fmaxf(sacc[nt][0], sacc[nt][1]));
                mn1 = fmaxf(mn1, fmaxf(sacc[nt][2], sacc[nt][3]));
            }
            mn0 = fmaxf(mn0, __shfl_xor_sync(0xffffffffu, mn0, 1));
            mn0 = fmaxf(mn0, __shfl_xor_sync(0xffffffffu, mn0, 2));
            mn1 = fmaxf(mn1, __shfl_xor_sync(0xffffffffu, mn1, 1));
            mn1 = fmaxf(mn1, __shfl_xor_sync(0xffffffffu, mn1, 2));
            float alpha0 = ex2(m0 - mn0);
            float alpha1 = ex2(m1 - mn1);
            m0 = mn0; m1 = mn1;

            float ls0 = 0.0f, ls1 = 0.0f;
#pragma unroll
            for (int nt = 0; nt < 8; ++nt) {
                sacc[nt][0] = ex2(sacc[nt][0] - mn0);
                sacc[nt][1] = ex2(sacc[nt][1] - mn0);
                sacc[nt][2] = ex2(sacc[nt][2] - mn1);
                sacc[nt][3] = ex2(sacc[nt][3] - mn1);
                ls0 += sacc[nt][0] + sacc[nt][1];
                ls1 += sacc[nt][2] + sacc[nt][3];
            }
            ls0 += __shfl_xor_sync(0xffffffffu, ls0, 1);
            ls0 += __shfl_xor_sync(0xffffffffu, ls0, 2);
            ls1 += __shfl_xor_sync(0xffffffffu, ls1, 1);
            ls1 += __shfl_xor_sync(0xffffffffu, ls1, 2);
            l0 = l0 * alpha0 + ls0;
            l1 = l1 * alpha1 + ls1;
#pragma unroll
            for (int nt = 0; nt < 8; ++nt) {
                oacc[nt][0] *= alpha0; oacc[nt][1] *= alpha0;
                oacc[nt][2] *= alpha1; oacc[nt][3] *= alpha1;
            }

            // ===== O += P @ V =====
#pragma unroll
            for (int t = 0; t < 4; ++t) {
                uint32_t ap[4], apl[4];
                packsplit(sacc[2*t][0],   sacc[2*t][1],   ap[0], apl[0]);
                packsplit(sacc[2*t][2],   sacc[2*t][3],   ap[1], apl[1]);
                packsplit(sacc[2*t+1][0], sacc[2*t+1][1], ap[2], apl[2]);
                packsplit(sacc[2*t+1][2], sacc[2*t+1][3], ap[3], apl[3]);
#pragma unroll
                for (int nt2 = 0; nt2 < 4; ++nt2) {
                    uint32_t bv[4], bvl[4];
                    int row = t * 16 + (lane & 15);
                    uint32_t off = swz128(row, nt2 * 2 + (lane >> 4));
                    ldsm_x4t(bv,  sVhi + off);
                    ldsm_x4t(bvl, sVlo + off);
                    mma_bf16(oacc[2*nt2],   ap,  bv);
                    mma_bf16(oacc[2*nt2],   ap,  bvl);
                    mma_bf16(oacc[2*nt2],   apl, bv);
                    mma_bf16(oacc[2*nt2+1], ap,  bv + 2);
                    mma_bf16(oacc[2*nt2+1], ap,  bvl + 2);
                    mma_bf16(oacc[2*nt2+1], apl, bv + 2);
                }
            }
        }

        // ===== epilogue =====
        float il0 = 1.0f / l0, il1 = 1.0f / l1;
        const size_t rb = ((size_t)(b * NHEAD + h) * SEQ + qt * 128 + wid * 16);
        const int er = lane >> 2, ec = (lane & 3) << 1;
#pragma unroll
        for (int nt = 0; nt < 8; ++nt) {
            uint32_t hv, lv;
            size_t p0 = (rb + er) * HDIM + nt * 8 + ec;
            packsplit(oacc[nt][0] * il0, oacc[nt][1] * il0, hv, lv);
            *(uint32_t*)(ohi + p0) = hv;
            *(uint32_t*)(olo + p0) = lv;
            size_t p1 = (rb + er + 8) * HDIM + nt * 8 + ec;
            packsplit(oacc[nt][2] * il1, oacc[nt][3] * il1, hv, lv);
            *(uint32_t*)(ohi + p1) = hv;
            *(uint32_t*)(olo + p1) = lv;
        }
    }
}

// ---------------------------------------------------------------------------
// Launch
// ---------------------------------------------------------------------------
extern "C" void kernel_launch(void* const* d_in, const int* in_sizes, int n_in,
                              void* d_out, int out_size)
{
    const float* x     = (const float*)d_in[0];
    const float* W_qkv = (const float*)d_in[1];
    const float* b_qkv = (const float*)d_in[2];
    const float* W_out = (const float*)d_in[3];
    const float* b_out = (const float*)d_in[4];
    const int*   maskp = (const int*)d_in[5];
    float* outp = (float*)d_out;

    __nv_bfloat16 *qkvhi, *qkvlo, *xhi, *xlo, *w1hi, *w1lo, *w2hi, *w2lo, *ohi, *olo;
    cudaGetSymbolAddress((void**)&qkvhi, g_qkvhi);
    cudaGetSymbolAddress((void**)&qkvlo, g_qkvlo);
    cudaGetSymbolAddress((void**)&xhi,  g_xhi);
    cudaGetSymbolAddress((void**)&xlo,  g_xlo);
    cudaGetSymbolAddress((void**)&w1hi, g_w1hi);
    cudaGetSymbolAddress((void**)&w1lo, g_w1lo);
    cudaGetSymbolAddress((void**)&w2hi, g_w2hi);
    cudaGetSymbolAddress((void**)&w2lo, g_w2lo);
    cudaGetSymbolAddress((void**)&ohi,  g_ohi);
    cudaGetSymbolAddress((void**)&olo,  g_olo);

    cudaFuncSetAttribute(gemm_bf16x3,
                         cudaFuncAttributeMaxDynamicSharedMemorySize, GSMEM);
    cudaFuncSetAttribute(gemm_bf16x3,
                         cudaFuncAttributePreferredSharedMemoryCarveout, 100);
    cudaFuncSetAttribute(attn_flash_hmma,
                         cudaFuncAttributeMaxDynamicSharedMemorySize, ASMEM);
    cudaFuncSetAttribute(attn_flash_hmma,
                         cudaFuncAttributePreferredSharedMemoryCarveout, 100);

    // 1) fused prep: split x + transpose/split both weight matrices
    prep_kernel<<<PREP_BLKS, 256>>>(x, xhi, xlo, W_qkv, w1hi, w1lo,
                                    W_out, w2hi, w2lo);

    // 2) QKV projection (persistent)
    {
        int nbx = TD / 128, ntiles = nbx * (MTOT / 128);
        gemm_bf16x3<<<NSM_X2, 256, GSMEM>>>(xhi, xlo, w1hi, w1lo, b_qkv,
                                            nullptr, qkvhi, qkvlo, 1,
                                            MTOT, TD, DMODEL, ntiles, nbx);
    }
    // 3) flash attention (persistent, balanced schedule)
    attn_flash_hmma<<<NSM_X2, 256, ASMEM>>>(qkvhi, qkvlo, ohi, olo, maskp);

    // 4) output projection (persistent)
    {
        int nbx = DMODEL / 128, ntiles = nbx * (MTOT / 128);
        gemm_bf16x3<<<NSM_X2, 256, GSMEM>>>(ohi, olo, w2hi, w2lo, b_out,
                                            outp, nullptr, nullptr, 0,
                                            MTOT, DMODEL, DMODEL, ntiles, nbx);
    }
}